// round 13
// baseline (speedup 1.0000x reference)
#include <cuda_runtime.h>

#define NN 16384
#define DEG 20
typedef unsigned long long u64;

__device__ float g_qt[NN * 32];
__device__ float g_L[NN * DEG];

static __device__ __forceinline__ u64 pk2(float lo, float hi) {
    u64 r; asm("mov.b64 %0, {%1, %2};" : "=l"(r) : "f"(lo), "f"(hi)); return r;
}
static __device__ __forceinline__ void upk2(u64 v, float& lo, float& hi) {
    asm("mov.b64 {%0, %1}, %2;" : "=f"(lo), "=f"(hi) : "l"(v));
}
static __device__ __forceinline__ u64 f2(u64 a, u64 b, u64 c) {
    u64 d; asm("fma.rn.f32x2 %0, %1, %2, %3;" : "=l"(d) : "l"(a), "l"(b), "l"(c)); return d;
}
static __device__ __forceinline__ u64 mul2(u64 a, u64 b) {
    u64 d; asm("mul.rn.f32x2 %0, %1, %2;" : "=l"(d) : "l"(a), "l"(b)); return d;
}
static __device__ __forceinline__ u64 add2(u64 a, u64 b) {
    u64 d; asm("add.rn.f32x2 %0, %1, %2;" : "=l"(d) : "l"(a), "l"(b)); return d;
}
static __device__ __forceinline__ float ss(float x) {
    return x > 0.f ? __expf(__fdividef(-1.f, x)) : 0.f;
}
static __device__ __forceinline__ float bsum(float v) {
#pragma unroll
    for (int o = 16; o >= 1; o >>= 1) v += __shfl_xor_sync(0xffffffffu, v, o);
    return v;
}

// ---------------- K0: fold Wq@Wd/sqrt(8) into per-node query ----------------
__global__ void k0_qt(const float* __restrict__ f, const float* __restrict__ Wq_s,
                      const float* __restrict__ Wq_v, const float* __restrict__ Wd_s,
                      const float* __restrict__ Wd_v) {
    __shared__ float As[64], Av[64];
    int t = threadIdx.x;
    if (t < 64) {
        int m = t >> 3, j = t & 7;
        float s = 0.f, v = 0.f;
#pragma unroll
        for (int o = 0; o < 8; o++) {
            s = fmaf(Wq_s[m * 8 + o], Wd_s[o * 8 + j], s);
            v = fmaf(Wq_v[m * 8 + o], Wd_v[o * 8 + j], v);
        }
        As[t] = s * 0.35355339059327373f;
        Av[t] = v * 0.35355339059327373f;
    }
    __syncthreads();
    int n = blockIdx.x * 256 + t;
    float fs[8], fv[24];
#pragma unroll
    for (int m = 0; m < 8; m++) fs[m] = f[n * 32 + m];
#pragma unroll
    for (int m = 0; m < 24; m++) fv[m] = f[n * 32 + 8 + m];
#pragma unroll
    for (int j = 0; j < 8; j++) {
        float s = 0.f;
#pragma unroll
        for (int m = 0; m < 8; m++) s = fmaf(fs[m], As[m * 8 + j], s);
        g_qt[n * 32 + j] = s;
    }
#pragma unroll
    for (int j = 0; j < 8; j++) {
        float v0 = 0.f, v1 = 0.f, v2 = 0.f;
#pragma unroll
        for (int m = 0; m < 8; m++) {
            float a = Av[m * 8 + j];
            v0 = fmaf(fv[m * 3 + 0], a, v0);
            v1 = fmaf(fv[m * 3 + 1], a, v1);
            v2 = fmaf(fv[m * 3 + 2], a, v2);
        }
        g_qt[n * 32 + 8 + j * 3 + 0] = v0;
        g_qt[n * 32 + 8 + j * 3 + 1] = v1;
        g_qt[n * 32 + 8 + j * 3 + 2] = v2;
    }
}

// shared layout constants (both kernels): W2 u64[64][129] | W1 640 fl | scratch
#define SM_W1 16512
#define SM_NS 17152
#define NS_STR 1864
#define F_OFF   0
#define EMB_OFF 1536
#define LC_OFF  1776
#define LG_OFF  1796
#define CO_OFF  1816
#define QV_OFF  1840
#define NTPB_A 512
#define NODES_A 16
#define NTPB_B 640
#define NODES_B 20
#define SMEM_A ((SM_NS + NODES_A * NS_STR) * 4)
#define SMEM_B ((SM_NS + NODES_B * NS_STR) * 4)

template <int NT>
static __device__ __forceinline__ void stage(float* sm, const float* W2,
                                             const float* W1, int tid) {
    u64* d = (u64*)sm;
    const u64* s = (const u64*)W2;
    for (int idx = tid; idx < 8192; idx += NT)
        d[(idx >> 7) * 129 + (idx & 127)] = s[idx];
    for (int i = tid; i < 640; i += NT) sm[SM_W1 + i] = W1[i];
}

// per-edge gather: F rows + emb (lanes 0-19)
static __device__ __forceinline__ void edge_setup(float* ws, const float* f,
                                                  const float* pos,
                                                  const int* edge_src, int n,
                                                  int lane, bool want_extra) {
    int e = lane;
    int src = edge_src[n * DEG + e];
    float dx = pos[src * 3 + 0] - pos[n * 3 + 0];
    float dy = pos[src * 3 + 1] - pos[n * 3 + 1];
    float dz = pos[src * 3 + 2] - pos[n * 3 + 2];
    float r2 = fmaf(dx, dx, fmaf(dy, dy, dz * dz));
    float ir = rsqrtf(r2);
    float r = r2 * ir;
    float uu[3] = {dx * ir, dy * ir, dz * ir};
    const float4* fp = (const float4*)(f + src * 32);
    float4 s0 = fp[0], s1 = fp[1];
    float gs[8] = {s0.x, s0.y, s0.z, s0.w, s1.x, s1.y, s1.z, s1.w};
    float gv[24];
    {
        float4 v0 = fp[2], v1 = fp[3], v2 = fp[4];
        float4 v3 = fp[5], v4 = fp[6], v5 = fp[7];
        gv[0]=v0.x; gv[1]=v0.y; gv[2]=v0.z; gv[3]=v0.w;
        gv[4]=v1.x; gv[5]=v1.y; gv[6]=v1.z; gv[7]=v1.w;
        gv[8]=v2.x; gv[9]=v2.y; gv[10]=v2.z; gv[11]=v2.w;
        gv[12]=v3.x; gv[13]=v3.y; gv[14]=v3.z; gv[15]=v3.w;
        gv[16]=v4.x; gv[17]=v4.y; gv[18]=v4.z; gv[19]=v4.w;
        gv[20]=v5.x; gv[21]=v5.y; gv[22]=v5.z; gv[23]=v5.w;
    }
    float* Ff = ws + F_OFF;
#pragma unroll
    for (int i = 0; i < 8; i++) {
        float gsi = gs[i];
        float g0 = gv[3 * i + 0], g1 = gv[3 * i + 1], g2 = gv[3 * i + 2];
        Ff[i * 24 + e] = gsi;
        Ff[(8 + i) * 24 + e] = fmaf(g0, uu[0], fmaf(g1, uu[1], g2 * uu[2]));
        Ff[(16 + i * 3 + 0) * 24 + e] = gsi * uu[0];
        Ff[(16 + i * 3 + 1) * 24 + e] = gsi * uu[1];
        Ff[(16 + i * 3 + 2) * 24 + e] = gsi * uu[2];
        Ff[(40 + i * 3 + 0) * 24 + e] = g0;
        Ff[(40 + i * 3 + 1) * 24 + e] = g1;
        Ff[(40 + i * 3 + 2) * 24 + e] = g2;
    }
    float rr = r * (11.0f / 3.5f);
#pragma unroll
    for (int b = 0; b < 10; b++) {
        float d = rr - (float)(b + 1);
        ws[EMB_OFF + b * 24 + e] = 26.66929f * ss(d + 1.f) * ss(1.f - d);
    }
    if (want_extra) {
        float x = 10.f * (1.f - r * (1.f / 3.5f));
        ws[LC_OFF + e] = (x > 0.f) ? -__fdividef(1.f, x) : -1e30f;
        ws[LG_OFF + e] = 0.f;
    }
}

static __device__ __forceinline__ void fc1_row(const float* ws, const float* W1s,
                                               int t, u64* h) {
    u64 acc[10];
    {
        float w = W1s[t];
        u64 wd = pk2(w, w);
        const ulonglong2* Er = (const ulonglong2*)(ws + EMB_OFF);
#pragma unroll
        for (int m = 0; m < 5; m++) {
            ulonglong2 p = Er[m];
            acc[2 * m] = mul2(wd, p.x);
            acc[2 * m + 1] = mul2(wd, p.y);
        }
    }
#pragma unroll
    for (int b = 1; b < 10; b++) {
        float w = W1s[b * 64 + t];
        u64 wd = pk2(w, w);
        const ulonglong2* Er = (const ulonglong2*)(ws + EMB_OFF + b * 24);
#pragma unroll
        for (int m = 0; m < 5; m++) {
            ulonglong2 p = Er[m];
            acc[2 * m] = f2(wd, p.x, acc[2 * m]);
            acc[2 * m + 1] = f2(wd, p.y, acc[2 * m + 1]);
        }
    }
#pragma unroll
    for (int m = 0; m < 10; m++) {
        float a0, a1;
        upk2(acc[m], a0, a1);
        a0 *= 0.31622776601683794f;
        a1 *= 0.31622776601683794f;
        h[m] = pk2(__fdividef(a0, 1.f + __expf(-a0)) * 0.125f,
                   __fdividef(a1, 1.f + __expf(-a1)) * 0.125f);
    }
}

static __device__ __forceinline__ void dupd(const float* ws, int xi, float M, u64* D) {
    u64 Md = pk2(M, M);
    const ulonglong2* Fr = (const ulonglong2*)(ws + F_OFF + xi * 24);
#pragma unroll
    for (int m = 0; m < 5; m++) {
        ulonglong2 p = Fr[m];
        D[2 * m] = f2(Md, p.x, D[2 * m]);
        D[2 * m + 1] = f2(Md, p.y, D[2 * m + 1]);
    }
}

static __device__ __forceinline__ float srow(const float* ws, int xi, const u64* hp) {
    const ulonglong2* Fr = (const ulonglong2*)(ws + F_OFF + xi * 24);
    u64 s0 = 0ULL, s1 = 0ULL;
#pragma unroll
    for (int m = 0; m < 5; m++) {
        ulonglong2 p = Fr[m];
        s0 = f2(hp[2 * m], p.x, s0);
        s1 = f2(hp[2 * m + 1], p.y, s1);
    }
    float lo, hi;
    upk2(add2(s0, s1), lo, hi);
    return lo + hi;
}

static __device__ __forceinline__ float dot8(const u64* wk, const u64* q) {
    u64 p0 = mul2(wk[0], q[0]);
    p0 = f2(wk[1], q[1], p0);
    u64 p1 = mul2(wk[2], q[2]);
    p1 = f2(wk[3], q[3], p1);
    float lo, hi;
    upk2(add2(p0, p1), lo, hi);
    return lo + hi;
}

static __device__ __forceinline__ float dot8qv(u64 w0, u64 w1, u64 w2, u64 w3,
                                               unsigned qsh) {
    u64 q0, q1, q2, q3;
    asm volatile("ld.shared.v2.u64 {%0, %1}, [%2];"
                 : "=l"(q0), "=l"(q1) : "r"(qsh));
    asm volatile("ld.shared.v2.u64 {%0, %1}, [%2];"
                 : "=l"(q2), "=l"(q3) : "r"(qsh + 16));
    u64 p0 = mul2(w0, q0);
    p0 = f2(w1, q1, p0);
    u64 p1 = mul2(w2, q2);
    p1 = f2(w3, q3, p1);
    float lo, hi;
    upk2(add2(p0, p1), lo, hi);
    return lo + hi;
}

// ================= Kernel A: k-net -> logits =================
__global__ __launch_bounds__(NTPB_A, 1) void se3_pass0(
    const float* __restrict__ f, const float* __restrict__ pos,
    const float* __restrict__ Wk1, const float* __restrict__ Wk2,
    const int* __restrict__ edge_src) {
    extern __shared__ float sm[];
    const int tid = threadIdx.x;
    const int wid = tid >> 5, lane = tid & 31;
    const int n = blockIdx.x * NODES_A + wid;
    float* ws = sm + SM_NS + wid * NS_STR;

    if (lane < 20) {
        edge_setup(ws, f, pos, edge_src, n, lane, true);
    } else if (lane < 23) {
        int c = lane - 20;
        const float* qf = g_qt + n * 32 + 8;
        u64* qd = (u64*)(ws + QV_OFF) + c * 4;
#pragma unroll
        for (int m = 0; m < 4; m++)
            qd[m] = pk2(qf[(2 * m) * 3 + c], qf[(2 * m + 1) * 3 + c]);
    }
    stage<NTPB_A>(sm, Wk2, Wk1, tid);
    __syncthreads();

    const unsigned qv_sh = (unsigned)__cvta_generic_to_shared(ws + QV_OFF);
    const u64* W2s64 = (const u64*)sm;
    const float* W1s = sm + SM_W1;

    u64 qq[4];
    {
        const u64* qsp = (const u64*)(g_qt + n * 32);
#pragma unroll
        for (int m = 0; m < 4; m++) qq[m] = qsp[m];
    }

#pragma unroll 1
    for (int half = 0; half < 2; half++) {
        int t = half * 32 + lane;
        u64 h[10], D[10];
        fc1_row(ws, W1s, t, h);
#pragma unroll
        for (int m = 0; m < 10; m++) D[m] = 0ULL;
        const u64* wrow = W2s64 + t * 129;
#pragma unroll 1
        for (int g = 0; g < 8; g++) {
            float M0 = dot8(wrow + (2 * g) * 4, qq);
            float M1 = dot8(wrow + (2 * g + 1) * 4, qq);
            dupd(ws, 2 * g, M0, D);
            dupd(ws, 2 * g + 1, M1, D);
        }
#pragma unroll 1
        for (int pi = 0; pi < 16; pi++) {
            const u64* wk = wrow + 64 + pi * 4;
            u64 w0 = wk[0], w1 = wk[1], w2 = wk[2], w3 = wk[3];
            int xb = 16 + (pi >> 3) * 24 + (pi & 7) * 3;
            float sc = (pi >= 8) ? 0.5773502691896258f : 1.0f;
#pragma unroll
            for (int c = 0; c < 3; c++)
                dupd(ws, xb + c,
                     dot8qv(w0, w1, w2, w3, qv_sh + c * 32) * sc, D);
        }
        // fold h into D, butterfly, accumulate into smem LG (no persistent Lacc)
#pragma unroll
        for (int m = 0; m < 10; m++) D[m] = mul2(h[m], D[m]);
#pragma unroll
        for (int o = 16; o >= 1; o >>= 1)
#pragma unroll
            for (int m = 0; m < 10; m++)
                D[m] = add2(D[m], __shfl_xor_sync(0xffffffffu, D[m], o));
        if (lane == 0) {
            u64* Lg = (u64*)(ws + LG_OFF);
#pragma unroll
            for (int m = 0; m < 10; m++) Lg[m] = add2(Lg[m], D[m]);
        }
        __syncwarp();
    }
    if (lane < 20)
        g_L[n * DEG + lane] =
            fmaf(0.022097086912079608f, ws[LG_OFF + lane], ws[LC_OFF + lane]);
}

// ================= Kernel B: softmax + v-net -> out =================
__global__ __launch_bounds__(NTPB_B, 1) void se3_pass1(
    const float* __restrict__ f, const float* __restrict__ pos,
    const float* __restrict__ Wv1, const float* __restrict__ Wv2,
    const int* __restrict__ edge_src, float* __restrict__ out) {
    extern __shared__ float sm[];
    const int tid = threadIdx.x;
    const int wid = tid >> 5, lane = tid & 31;
    const int n = blockIdx.x * NODES_B + wid;
    const bool active = (n < NN);
    float* ws = sm + SM_NS + wid * NS_STR;

    if (active && lane < 20) edge_setup(ws, f, pos, edge_src, n, lane, false);
    stage<NTPB_B>(sm, Wv2, Wv1, tid);
    __syncthreads();

    const unsigned co_sh = (unsigned)__cvta_generic_to_shared(ws + CO_OFF);

    if (active) {
        // in-warp softmax from g_L; coef folds 0.25 tp norm
        {
            float L = (lane < 20) ? g_L[n * DEG + lane] : -3.0e38f;
            float M = L;
#pragma unroll
            for (int o = 16; o >= 1; o >>= 1)
                M = fmaxf(M, __shfl_xor_sync(0xffffffffu, M, o));
            float ex = (lane < 20) ? __expf(L - M) : 0.f;
            float z = bsum(ex);
            if (lane < 20)
                ws[CO_OFF + lane] = 0.25f * sqrtf(__fdividef(ex, z) + 1e-12f);
        }
        __syncwarp();

        const u64* W2s64 = (const u64*)sm;
        const float* W1s = sm + SM_W1;
        u64 os[4] = {0ULL, 0ULL, 0ULL, 0ULL};
        u64 ov[3][4] = {};

#pragma unroll 1
        for (int half = 0; half < 2; half++) {
            int t = half * 32 + lane;
            u64 h[10];
            fc1_row(ws, W1s, t, h);
#pragma unroll
            for (int m = 0; m < 10; m++) {
                u64 cm;
                asm volatile("ld.shared.b64 %0, [%1];"
                             : "=l"(cm) : "r"(co_sh + m * 8));
                h[m] = mul2(h[m], cm);
            }
            const u64* wrow = W2s64 + t * 129;
#pragma unroll 1
            for (int g = 0; g < 8; g++) {
                float S0 = srow(ws, 2 * g, h);
                float S1 = srow(ws, 2 * g + 1, h);
                u64 Sd0 = pk2(S0, S0), Sd1 = pk2(S1, S1);
                const u64* wk0 = wrow + (2 * g) * 4;
                const u64* wk1 = wrow + (2 * g + 1) * 4;
#pragma unroll
                for (int r = 0; r < 4; r++) os[r] = f2(Sd0, wk0[r], os[r]);
#pragma unroll
                for (int r = 0; r < 4; r++) os[r] = f2(Sd1, wk1[r], os[r]);
            }
#pragma unroll 1
            for (int pi = 0; pi < 16; pi++) {
                const u64* wk = wrow + 64 + pi * 4;
                u64 w0 = wk[0], w1 = wk[1], w2 = wk[2], w3 = wk[3];
                int xb = 16 + (pi >> 3) * 24 + (pi & 7) * 3;
                float sc = (pi < 8) ? 1.7320508075688772f : 1.0f;
#pragma unroll
                for (int c = 0; c < 3; c++) {
                    float S = srow(ws, xb + c, h) * sc;
                    u64 Sd = pk2(S, S);
                    ov[c][0] = f2(Sd, w0, ov[c][0]);
                    ov[c][1] = f2(Sd, w1, ov[c][1]);
                    ov[c][2] = f2(Sd, w2, ov[c][2]);
                    ov[c][3] = f2(Sd, w3, ov[c][3]);
                }
            }
        }
#pragma unroll
        for (int o = 16; o >= 1; o >>= 1) {
#pragma unroll
            for (int r = 0; r < 4; r++)
                os[r] = add2(os[r], __shfl_xor_sync(0xffffffffu, os[r], o));
#pragma unroll
            for (int c = 0; c < 3; c++)
#pragma unroll
                for (int r = 0; r < 4; r++)
                    ov[c][r] = add2(ov[c][r], __shfl_xor_sync(0xffffffffu, ov[c][r], o));
        }
        if (lane < 4) {
            float a, b;
            upk2(os[lane], a, b);
            out[n * 32 + 2 * lane] = a;
            out[n * 32 + 2 * lane + 1] = b;
        } else if (lane < 16) {
            int idx = lane - 4;
            int c = idx >> 2, r = idx & 3;
            float a, b;
            upk2(ov[c][r], a, b);
            out[n * 32 + 8 + (2 * r) * 3 + c] = a;
            out[n * 32 + 8 + (2 * r + 1) * 3 + c] = b;
        }
    }
}

extern "C" void kernel_launch(void* const* d_in, const int* in_sizes, int n_in,
                              void* d_out, int out_size) {
    const float* f    = (const float*)d_in[0];
    const float* pos  = (const float*)d_in[1];
    const float* Wq_s = (const float*)d_in[2];
    const float* Wq_v = (const float*)d_in[3];
    const float* Wk1  = (const float*)d_in[4];
    const float* Wk2  = (const float*)d_in[5];
    const float* Wv1  = (const float*)d_in[6];
    const float* Wv2  = (const float*)d_in[7];
    const float* Wd_s = (const float*)d_in[8];
    const float* Wd_v = (const float*)d_in[9];
    const int* esrc   = (const int*)d_in[10];
    float* out = (float*)d_out;

    cudaFuncSetAttribute(se3_pass0, cudaFuncAttributeMaxDynamicSharedMemorySize, SMEM_A);
    cudaFuncSetAttribute(se3_pass1, cudaFuncAttributeMaxDynamicSharedMemorySize, SMEM_B);
    k0_qt<<<64, 256>>>(f, Wq_s, Wq_v, Wd_s, Wd_v);
    se3_pass0<<<NN / NODES_A, NTPB_A, SMEM_A>>>(f, pos, Wk1, Wk2, esrc);
    se3_pass1<<<(NN + NODES_B - 1) / NODES_B, NTPB_B, SMEM_B>>>(f, pos, Wv1, Wv2,
                                                               esrc, out);
}

// round 14
// speedup vs baseline: 1.0658x; 1.0658x over previous
#include <cuda_runtime.h>

#define NN 16384
#define DEG 20
typedef unsigned long long u64;

__device__ float g_qt[NN * 32];
__device__ float g_L[NN * DEG];

static __device__ __forceinline__ u64 pk2(float lo, float hi) {
    u64 r; asm("mov.b64 %0, {%1, %2};" : "=l"(r) : "f"(lo), "f"(hi)); return r;
}
static __device__ __forceinline__ void upk2(u64 v, float& lo, float& hi) {
    asm("mov.b64 {%0, %1}, %2;" : "=f"(lo), "=f"(hi) : "l"(v));
}
static __device__ __forceinline__ u64 f2(u64 a, u64 b, u64 c) {
    u64 d; asm("fma.rn.f32x2 %0, %1, %2, %3;" : "=l"(d) : "l"(a), "l"(b), "l"(c)); return d;
}
static __device__ __forceinline__ u64 mul2(u64 a, u64 b) {
    u64 d; asm("mul.rn.f32x2 %0, %1, %2;" : "=l"(d) : "l"(a), "l"(b)); return d;
}
static __device__ __forceinline__ u64 add2(u64 a, u64 b) {
    u64 d; asm("add.rn.f32x2 %0, %1, %2;" : "=l"(d) : "l"(a), "l"(b)); return d;
}
static __device__ __forceinline__ float ss(float x) {
    return x > 0.f ? __expf(__fdividef(-1.f, x)) : 0.f;
}
static __device__ __forceinline__ float bsum(float v) {
#pragma unroll
    for (int o = 16; o >= 1; o >>= 1) v += __shfl_xor_sync(0xffffffffu, v, o);
    return v;
}

// ---------------- K0: fold Wq@Wd/sqrt(8) into per-node query ----------------
__global__ void k0_qt(const float* __restrict__ f, const float* __restrict__ Wq_s,
                      const float* __restrict__ Wq_v, const float* __restrict__ Wd_s,
                      const float* __restrict__ Wd_v) {
    __shared__ float As[64], Av[64];
    int t = threadIdx.x;
    if (t < 64) {
        int m = t >> 3, j = t & 7;
        float s = 0.f, v = 0.f;
#pragma unroll
        for (int o = 0; o < 8; o++) {
            s = fmaf(Wq_s[m * 8 + o], Wd_s[o * 8 + j], s);
            v = fmaf(Wq_v[m * 8 + o], Wd_v[o * 8 + j], v);
        }
        As[t] = s * 0.35355339059327373f;
        Av[t] = v * 0.35355339059327373f;
    }
    __syncthreads();
    int n = blockIdx.x * 128 + t;
    float fs[8], fv[24];
#pragma unroll
    for (int m = 0; m < 8; m++) fs[m] = f[n * 32 + m];
#pragma unroll
    for (int m = 0; m < 24; m++) fv[m] = f[n * 32 + 8 + m];
#pragma unroll
    for (int j = 0; j < 8; j++) {
        float s = 0.f;
#pragma unroll
        for (int m = 0; m < 8; m++) s = fmaf(fs[m], As[m * 8 + j], s);
        g_qt[n * 32 + j] = s;
    }
#pragma unroll
    for (int j = 0; j < 8; j++) {
        float v0 = 0.f, v1 = 0.f, v2 = 0.f;
#pragma unroll
        for (int m = 0; m < 8; m++) {
            float a = Av[m * 8 + j];
            v0 = fmaf(fv[m * 3 + 0], a, v0);
            v1 = fmaf(fv[m * 3 + 1], a, v1);
            v2 = fmaf(fv[m * 3 + 2], a, v2);
        }
        g_qt[n * 32 + 8 + j * 3 + 0] = v0;
        g_qt[n * 32 + 8 + j * 3 + 1] = v1;
        g_qt[n * 32 + 8 + j * 3 + 2] = v2;
    }
}

// shared layout: W2 u64[64][129] | W1 640 fl | node scratch
#define SM_W1 16512
#define SM_NS 17152
#define NS_STR 1864
#define F_OFF   0
#define EMB_OFF 1536
#define LC_OFF  1776
#define CO_OFF  1816
#define QV_OFF  1840
#define NTPB_A 384
#define NODES_A 12
#define NTPB_B 512
#define NODES_B 16
#define SMEM_A ((SM_NS + NODES_A * NS_STR) * 4)
#define SMEM_B ((SM_NS + NODES_B * NS_STR) * 4)

template <int NT>
static __device__ __forceinline__ void stage(float* sm, const float* W2,
                                             const float* W1, int tid) {
    u64* d = (u64*)sm;
    const u64* s = (const u64*)W2;
    for (int idx = tid; idx < 8192; idx += NT)
        d[(idx >> 7) * 129 + (idx & 127)] = s[idx];
    for (int i = tid; i < 640; i += NT) sm[SM_W1 + i] = W1[i];
}

// per-edge gather: F rows + emb (lanes 0-19)
static __device__ __forceinline__ void edge_setup(float* ws, const float* f,
                                                  const float* pos,
                                                  const int* edge_src, int n,
                                                  int lane, bool want_lc) {
    int e = lane;
    int src = edge_src[n * DEG + e];
    float dx = pos[src * 3 + 0] - pos[n * 3 + 0];
    float dy = pos[src * 3 + 1] - pos[n * 3 + 1];
    float dz = pos[src * 3 + 2] - pos[n * 3 + 2];
    float r2 = fmaf(dx, dx, fmaf(dy, dy, dz * dz));
    float ir = rsqrtf(r2);
    float r = r2 * ir;
    float uu[3] = {dx * ir, dy * ir, dz * ir};
    const float4* fp = (const float4*)(f + src * 32);
    float4 s0 = fp[0], s1 = fp[1];
    float gs[8] = {s0.x, s0.y, s0.z, s0.w, s1.x, s1.y, s1.z, s1.w};
    float gv[24];
    {
        float4 v0 = fp[2], v1 = fp[3], v2 = fp[4];
        float4 v3 = fp[5], v4 = fp[6], v5 = fp[7];
        gv[0]=v0.x; gv[1]=v0.y; gv[2]=v0.z; gv[3]=v0.w;
        gv[4]=v1.x; gv[5]=v1.y; gv[6]=v1.z; gv[7]=v1.w;
        gv[8]=v2.x; gv[9]=v2.y; gv[10]=v2.z; gv[11]=v2.w;
        gv[12]=v3.x; gv[13]=v3.y; gv[14]=v3.z; gv[15]=v3.w;
        gv[16]=v4.x; gv[17]=v4.y; gv[18]=v4.z; gv[19]=v4.w;
        gv[20]=v5.x; gv[21]=v5.y; gv[22]=v5.z; gv[23]=v5.w;
    }
    float* Ff = ws + F_OFF;
#pragma unroll
    for (int i = 0; i < 8; i++) {
        float gsi = gs[i];
        float g0 = gv[3 * i + 0], g1 = gv[3 * i + 1], g2 = gv[3 * i + 2];
        Ff[i * 24 + e] = gsi;
        Ff[(8 + i) * 24 + e] = fmaf(g0, uu[0], fmaf(g1, uu[1], g2 * uu[2]));
        Ff[(16 + i * 3 + 0) * 24 + e] = gsi * uu[0];
        Ff[(16 + i * 3 + 1) * 24 + e] = gsi * uu[1];
        Ff[(16 + i * 3 + 2) * 24 + e] = gsi * uu[2];
        Ff[(40 + i * 3 + 0) * 24 + e] = g0;
        Ff[(40 + i * 3 + 1) * 24 + e] = g1;
        Ff[(40 + i * 3 + 2) * 24 + e] = g2;
    }
    float rr = r * (11.0f / 3.5f);
#pragma unroll
    for (int b = 0; b < 10; b++) {
        float d = rr - (float)(b + 1);
        ws[EMB_OFF + b * 24 + e] = 26.66929f * ss(d + 1.f) * ss(1.f - d);
    }
    if (want_lc) {
        float x = 10.f * (1.f - r * (1.f / 3.5f));
        ws[LC_OFF + e] = (x > 0.f) ? -__fdividef(1.f, x) : -1e30f;
    }
}

static __device__ __forceinline__ void fc1_row(const float* ws, const float* W1s,
                                               int t, u64* h) {
    u64 acc[10];
    {
        float w = W1s[t];
        u64 wd = pk2(w, w);
        const ulonglong2* Er = (const ulonglong2*)(ws + EMB_OFF);
#pragma unroll
        for (int m = 0; m < 5; m++) {
            ulonglong2 p = Er[m];
            acc[2 * m] = mul2(wd, p.x);
            acc[2 * m + 1] = mul2(wd, p.y);
        }
    }
#pragma unroll
    for (int b = 1; b < 10; b++) {
        float w = W1s[b * 64 + t];
        u64 wd = pk2(w, w);
        const ulonglong2* Er = (const ulonglong2*)(ws + EMB_OFF + b * 24);
#pragma unroll
        for (int m = 0; m < 5; m++) {
            ulonglong2 p = Er[m];
            acc[2 * m] = f2(wd, p.x, acc[2 * m]);
            acc[2 * m + 1] = f2(wd, p.y, acc[2 * m + 1]);
        }
    }
#pragma unroll
    for (int m = 0; m < 10; m++) {
        float a0, a1;
        upk2(acc[m], a0, a1);
        a0 *= 0.31622776601683794f;
        a1 *= 0.31622776601683794f;
        h[m] = pk2(__fdividef(a0, 1.f + __expf(-a0)) * 0.125f,
                   __fdividef(a1, 1.f + __expf(-a1)) * 0.125f);
    }
}

static __device__ __forceinline__ void dupd(const float* ws, int xi, float M, u64* D) {
    u64 Md = pk2(M, M);
    const ulonglong2* Fr = (const ulonglong2*)(ws + F_OFF + xi * 24);
#pragma unroll
    for (int m = 0; m < 5; m++) {
        ulonglong2 p = Fr[m];
        D[2 * m] = f2(Md, p.x, D[2 * m]);
        D[2 * m + 1] = f2(Md, p.y, D[2 * m + 1]);
    }
}

static __device__ __forceinline__ float srow(const float* ws, int xi, const u64* hp) {
    const ulonglong2* Fr = (const ulonglong2*)(ws + F_OFF + xi * 24);
    u64 s0 = 0ULL, s1 = 0ULL;
#pragma unroll
    for (int m = 0; m < 5; m++) {
        ulonglong2 p = Fr[m];
        s0 = f2(hp[2 * m], p.x, s0);
        s1 = f2(hp[2 * m + 1], p.y, s1);
    }
    float lo, hi;
    upk2(add2(s0, s1), lo, hi);
    return lo + hi;
}

static __device__ __forceinline__ float dot8(const u64* wk, const u64* q) {
    u64 p0 = mul2(wk[0], q[0]);
    p0 = f2(wk[1], q[1], p0);
    u64 p1 = mul2(wk[2], q[2]);
    p1 = f2(wk[3], q[3], p1);
    float lo, hi;
    upk2(add2(p0, p1), lo, hi);
    return lo + hi;
}

static __device__ __forceinline__ float dot8qv(u64 w0, u64 w1, u64 w2, u64 w3,
                                               unsigned qsh) {
    u64 q0, q1, q2, q3;
    asm volatile("ld.shared.v2.u64 {%0, %1}, [%2];"
                 : "=l"(q0), "=l"(q1) : "r"(qsh));
    asm volatile("ld.shared.v2.u64 {%0, %1}, [%2];"
                 : "=l"(q2), "=l"(q3) : "r"(qsh + 16));
    u64 p0 = mul2(w0, q0);
    p0 = f2(w1, q1, p0);
    u64 p1 = mul2(w2, q2);
    p1 = f2(w3, q3, p1);
    float lo, hi;
    upk2(add2(p0, p1), lo, hi);
    return lo + hi;
}

// ================= Kernel A: k-net -> logits (384 thr, R12 body) =================
__global__ __launch_bounds__(NTPB_A, 1) void se3_pass0(
    const float* __restrict__ f, const float* __restrict__ pos,
    const float* __restrict__ Wk1, const float* __restrict__ Wk2,
    const int* __restrict__ edge_src) {
    extern __shared__ float sm[];
    const int tid = threadIdx.x;
    const int wid = tid >> 5, lane = tid & 31;
    const int n = blockIdx.x * NODES_A + wid;
    const bool active = (n < NN);
    float* ws = sm + SM_NS + wid * NS_STR;

    if (active) {
        if (lane < 20) {
            edge_setup(ws, f, pos, edge_src, n, lane, true);
        } else if (lane < 23) {
            int c = lane - 20;
            const float* qf = g_qt + n * 32 + 8;
            u64* qd = (u64*)(ws + QV_OFF) + c * 4;
#pragma unroll
            for (int m = 0; m < 4; m++)
                qd[m] = pk2(qf[(2 * m) * 3 + c], qf[(2 * m + 1) * 3 + c]);
        }
    }
    stage<NTPB_A>(sm, Wk2, Wk1, tid);
    __syncthreads();

    if (!active) return;
    const unsigned qv_sh = (unsigned)__cvta_generic_to_shared(ws + QV_OFF);
    const u64* W2s64 = (const u64*)sm;
    const float* W1s = sm + SM_W1;

    u64 qq[4];
    {
        const u64* qsp = (const u64*)(g_qt + n * 32);
#pragma unroll
        for (int m = 0; m < 4; m++) qq[m] = qsp[m];
    }
    u64 Lacc[10];
#pragma unroll
    for (int m = 0; m < 10; m++) Lacc[m] = 0ULL;

#pragma unroll 1
    for (int half = 0; half < 2; half++) {
        int t = half * 32 + lane;
        u64 h[10], D[10];
        fc1_row(ws, W1s, t, h);
#pragma unroll
        for (int m = 0; m < 10; m++) D[m] = 0ULL;
        const u64* wrow = W2s64 + t * 129;
#pragma unroll 1
        for (int g = 0; g < 8; g++) {
            float M0 = dot8(wrow + (2 * g) * 4, qq);
            float M1 = dot8(wrow + (2 * g + 1) * 4, qq);
            dupd(ws, 2 * g, M0, D);
            dupd(ws, 2 * g + 1, M1, D);
        }
#pragma unroll 1
        for (int pi = 0; pi < 16; pi++) {
            const u64* wk = wrow + 64 + pi * 4;
            u64 w0 = wk[0], w1 = wk[1], w2 = wk[2], w3 = wk[3];
            int xb = 16 + (pi >> 3) * 24 + (pi & 7) * 3;
            float sc = (pi >= 8) ? 0.5773502691896258f : 1.0f;
#pragma unroll
            for (int c = 0; c < 3; c++)
                dupd(ws, xb + c,
                     dot8qv(w0, w1, w2, w3, qv_sh + c * 32) * sc, D);
        }
#pragma unroll
        for (int m = 0; m < 10; m++) Lacc[m] = f2(h[m], D[m], Lacc[m]);
    }
#pragma unroll
    for (int o = 16; o >= 1; o >>= 1)
#pragma unroll
        for (int m = 0; m < 10; m++)
            Lacc[m] = add2(Lacc[m], __shfl_xor_sync(0xffffffffu, Lacc[m], o));
    // lane 2m holds pair (e=2m, e=2m+1) after full butterfly? No: butterfly sums
    // across all lanes; every lane has the same Lacc. Lane < 20 writes its edge.
    if (lane < 20) {
        int m = lane >> 1;
        float lo, hi;
        upk2(Lacc[m], lo, hi);
        float Lg = (lane & 1) ? hi : lo;
        g_L[n * DEG + lane] =
            fmaf(0.022097086912079608f, Lg, ws[LC_OFF + lane]);
    }
}

// ================= Kernel B: softmax + v-net -> out (512 thr) =================
__global__ __launch_bounds__(NTPB_B, 1) void se3_pass1(
    const float* __restrict__ f, const float* __restrict__ pos,
    const float* __restrict__ Wv1, const float* __restrict__ Wv2,
    const int* __restrict__ edge_src, float* __restrict__ out) {
    extern __shared__ float sm[];
    const int tid = threadIdx.x;
    const int wid = tid >> 5, lane = tid & 31;
    const int n = blockIdx.x * NODES_B + wid;
    const bool active = (n < NN);
    float* ws = sm + SM_NS + wid * NS_STR;

    if (active && lane < 20) edge_setup(ws, f, pos, edge_src, n, lane, false);
    stage<NTPB_B>(sm, Wv2, Wv1, tid);
    __syncthreads();

    if (!active) return;
    const unsigned co_sh = (unsigned)__cvta_generic_to_shared(ws + CO_OFF);

    // in-warp softmax from g_L; coef folds 0.25 tp norm
    {
        float L = (lane < 20) ? g_L[n * DEG + lane] : -3.0e38f;
        float M = L;
#pragma unroll
        for (int o = 16; o >= 1; o >>= 1)
            M = fmaxf(M, __shfl_xor_sync(0xffffffffu, M, o));
        float ex = (lane < 20) ? __expf(L - M) : 0.f;
        float z = bsum(ex);
        if (lane < 20)
            ws[CO_OFF + lane] = 0.25f * sqrtf(__fdividef(ex, z) + 1e-12f);
    }
    __syncwarp();

    const u64* W2s64 = (const u64*)sm;
    const float* W1s = sm + SM_W1;
    u64 os[4] = {0ULL, 0ULL, 0ULL, 0ULL};
    u64 ov[3][4] = {};

#pragma unroll 1
    for (int half = 0; half < 2; half++) {
        int t = half * 32 + lane;
        u64 h[10];
        fc1_row(ws, W1s, t, h);
#pragma unroll
        for (int m = 0; m < 10; m++) {
            u64 cm;
            asm volatile("ld.shared.b64 %0, [%1];"
                         : "=l"(cm) : "r"(co_sh + m * 8));
            h[m] = mul2(h[m], cm);
        }
        const u64* wrow = W2s64 + t * 129;
#pragma unroll 1
        for (int g = 0; g < 8; g++) {
            float S0 = srow(ws, 2 * g, h);
            float S1 = srow(ws, 2 * g + 1, h);
            u64 Sd0 = pk2(S0, S0), Sd1 = pk2(S1, S1);
            const u64* wk0 = wrow + (2 * g) * 4;
            const u64* wk1 = wrow + (2 * g + 1) * 4;
#pragma unroll
            for (int r = 0; r < 4; r++) os[r] = f2(Sd0, wk0[r], os[r]);
#pragma unroll
            for (int r = 0; r < 4; r++) os[r] = f2(Sd1, wk1[r], os[r]);
        }
#pragma unroll 1
        for (int pi = 0; pi < 16; pi++) {
            const u64* wk = wrow + 64 + pi * 4;
            u64 w0 = wk[0], w1 = wk[1], w2 = wk[2], w3 = wk[3];
            int xb = 16 + (pi >> 3) * 24 + (pi & 7) * 3;
            float sc = (pi < 8) ? 1.7320508075688772f : 1.0f;
#pragma unroll
            for (int c = 0; c < 3; c++) {
                float S = srow(ws, xb + c, h) * sc;
                u64 Sd = pk2(S, S);
                ov[c][0] = f2(Sd, w0, ov[c][0]);
                ov[c][1] = f2(Sd, w1, ov[c][1]);
                ov[c][2] = f2(Sd, w2, ov[c][2]);
                ov[c][3] = f2(Sd, w3, ov[c][3]);
            }
        }
    }
#pragma unroll
    for (int o = 16; o >= 1; o >>= 1) {
#pragma unroll
        for (int r = 0; r < 4; r++)
            os[r] = add2(os[r], __shfl_xor_sync(0xffffffffu, os[r], o));
#pragma unroll
        for (int c = 0; c < 3; c++)
#pragma unroll
            for (int r = 0; r < 4; r++)
                ov[c][r] = add2(ov[c][r], __shfl_xor_sync(0xffffffffu, ov[c][r], o));
    }
    if (lane < 4) {
        float a, b;
        upk2(os[lane], a, b);
        out[n * 32 + 2 * lane] = a;
        out[n * 32 + 2 * lane + 1] = b;
    } else if (lane < 16) {
        int idx = lane - 4;
        int c = idx >> 2, r = idx & 3;
        float a, b;
        upk2(ov[c][r], a, b);
        out[n * 32 + 8 + (2 * r) * 3 + c] = a;
        out[n * 32 + 8 + (2 * r + 1) * 3 + c] = b;
    }
}

extern "C" void kernel_launch(void* const* d_in, const int* in_sizes, int n_in,
                              void* d_out, int out_size) {
    const float* f    = (const float*)d_in[0];
    const float* pos  = (const float*)d_in[1];
    const float* Wq_s = (const float*)d_in[2];
    const float* Wq_v = (const float*)d_in[3];
    const float* Wk1  = (const float*)d_in[4];
    const float* Wk2  = (const float*)d_in[5];
    const float* Wv1  = (const float*)d_in[6];
    const float* Wv2  = (const float*)d_in[7];
    const float* Wd_s = (const float*)d_in[8];
    const float* Wd_v = (const float*)d_in[9];
    const int* esrc   = (const int*)d_in[10];
    float* out = (float*)d_out;

    cudaFuncSetAttribute(se3_pass0, cudaFuncAttributeMaxDynamicSharedMemorySize, SMEM_A);
    cudaFuncSetAttribute(se3_pass1, cudaFuncAttributeMaxDynamicSharedMemorySize, SMEM_B);
    k0_qt<<<128, 128>>>(f, Wq_s, Wq_v, Wd_s, Wd_v);
    se3_pass0<<<(NN + NODES_A - 1) / NODES_A, NTPB_A, SMEM_A>>>(f, pos, Wk1, Wk2, esrc);
    se3_pass1<<<(NN + NODES_B - 1) / NODES_B, NTPB_B, SMEM_B>>>(f, pos, Wv1, Wv2,
                                                               esrc, out);
}

// round 15
// speedup vs baseline: 1.1395x; 1.0691x over previous
#include <cuda_runtime.h>

#define NN 16384
#define DEG 20
typedef unsigned long long u64;

__device__ float g_qt[NN * 32];

static __device__ __forceinline__ u64 pk2(float lo, float hi) {
    u64 r; asm("mov.b64 %0, {%1, %2};" : "=l"(r) : "f"(lo), "f"(hi)); return r;
}
static __device__ __forceinline__ void upk2(u64 v, float& lo, float& hi) {
    asm("mov.b64 {%0, %1}, %2;" : "=f"(lo), "=f"(hi) : "l"(v));
}
static __device__ __forceinline__ u64 f2(u64 a, u64 b, u64 c) {
    u64 d; asm("fma.rn.f32x2 %0, %1, %2, %3;" : "=l"(d) : "l"(a), "l"(b), "l"(c)); return d;
}
static __device__ __forceinline__ u64 mul2(u64 a, u64 b) {
    u64 d; asm("mul.rn.f32x2 %0, %1, %2;" : "=l"(d) : "l"(a), "l"(b)); return d;
}
static __device__ __forceinline__ u64 add2(u64 a, u64 b) {
    u64 d; asm("add.rn.f32x2 %0, %1, %2;" : "=l"(d) : "l"(a), "l"(b)); return d;
}
static __device__ __forceinline__ float ss(float x) {
    return x > 0.f ? __expf(__fdividef(-1.f, x)) : 0.f;
}
static __device__ __forceinline__ float bsum(float v) {
#pragma unroll
    for (int o = 16; o >= 1; o >>= 1) v += __shfl_xor_sync(0xffffffffu, v, o);
    return v;
}

// ---------------- K0: fold Wq@Wd/sqrt(8) into per-node query ----------------
__global__ void k0_qt(const float* __restrict__ f, const float* __restrict__ Wq_s,
                      const float* __restrict__ Wq_v, const float* __restrict__ Wd_s,
                      const float* __restrict__ Wd_v) {
    __shared__ float As[64], Av[64];
    int t = threadIdx.x;
    if (t < 64) {
        int m = t >> 3, j = t & 7;
        float s = 0.f, v = 0.f;
#pragma unroll
        for (int o = 0; o < 8; o++) {
            s = fmaf(Wq_s[m * 8 + o], Wd_s[o * 8 + j], s);
            v = fmaf(Wq_v[m * 8 + o], Wd_v[o * 8 + j], v);
        }
        As[t] = s * 0.35355339059327373f;
        Av[t] = v * 0.35355339059327373f;
    }
    __syncthreads();
    int n = blockIdx.x * 128 + t;
    float fs[8], fv[24];
#pragma unroll
    for (int m = 0; m < 8; m++) fs[m] = f[n * 32 + m];
#pragma unroll
    for (int m = 0; m < 24; m++) fv[m] = f[n * 32 + 8 + m];
#pragma unroll
    for (int j = 0; j < 8; j++) {
        float s = 0.f;
#pragma unroll
        for (int m = 0; m < 8; m++) s = fmaf(fs[m], As[m * 8 + j], s);
        g_qt[n * 32 + j] = s;
    }
#pragma unroll
    for (int j = 0; j < 8; j++) {
        float v0 = 0.f, v1 = 0.f, v2 = 0.f;
#pragma unroll
        for (int m = 0; m < 8; m++) {
            float a = Av[m * 8 + j];
            v0 = fmaf(fv[m * 3 + 0], a, v0);
            v1 = fmaf(fv[m * 3 + 1], a, v1);
            v2 = fmaf(fv[m * 3 + 2], a, v2);
        }
        g_qt[n * 32 + 8 + j * 3 + 0] = v0;
        g_qt[n * 32 + 8 + j * 3 + 1] = v1;
        g_qt[n * 32 + 8 + j * 3 + 2] = v2;
    }
}

// smem: W2k u64[64][130] | W2v u64[64][130] | W1k 640 | W1v 640 | 12 node scratch
#define SM_W2V 16640
#define SM_W1K 33280
#define SM_W1V 33920
#define SM_NS  34560
#define NS_STR 1864
#define F_OFF   0     // [64][24] rows: gs(0-7) gd(8-15) su(16-39) gv(40-63)
#define EMB_OFF 1536  // [10][24]
#define LC_OFF  1776
#define LG_OFF  1796
#define CO_OFF  1816
#define QV_OFF  1840  // [3][4] u64 = 24 floats, 16B aligned
#define NTPB 384
#define NODES_PB 12
#define SMEM_BYTES ((SM_NS + NODES_PB * NS_STR) * 4)

// stage both nets once (stride 130 u64: rows 16B aligned, conflict-free LDS.128)
static __device__ __forceinline__ void stage_all(float* sm, const float* Wk2,
                                                 const float* Wv2, const float* Wk1,
                                                 const float* Wv1, int tid) {
    u64* dk = (u64*)sm;
    u64* dv = (u64*)(sm + SM_W2V);
    const u64* sk = (const u64*)Wk2;
    const u64* sv = (const u64*)Wv2;
    for (int idx = tid; idx < 8192; idx += NTPB) {
        int o = (idx >> 7) * 130 + (idx & 127);
        dk[o] = sk[idx];
        dv[o] = sv[idx];
    }
    for (int i = tid; i < 640; i += NTPB) {
        sm[SM_W1K + i] = Wk1[i];
        sm[SM_W1V + i] = Wv1[i];
    }
}

// h pairs over 20 edges for hidden unit t (folds /sqrt(10), silu, /8)
static __device__ __forceinline__ void fc1_row(const float* ws, const float* W1s,
                                               int t, u64* h) {
    u64 acc[10];
    {
        float w = W1s[t];
        u64 wd = pk2(w, w);
        const ulonglong2* Er = (const ulonglong2*)(ws + EMB_OFF);
#pragma unroll
        for (int m = 0; m < 5; m++) {
            ulonglong2 p = Er[m];
            acc[2 * m] = mul2(wd, p.x);
            acc[2 * m + 1] = mul2(wd, p.y);
        }
    }
#pragma unroll
    for (int b = 1; b < 10; b++) {
        float w = W1s[b * 64 + t];
        u64 wd = pk2(w, w);
        const ulonglong2* Er = (const ulonglong2*)(ws + EMB_OFF + b * 24);
#pragma unroll
        for (int m = 0; m < 5; m++) {
            ulonglong2 p = Er[m];
            acc[2 * m] = f2(wd, p.x, acc[2 * m]);
            acc[2 * m + 1] = f2(wd, p.y, acc[2 * m + 1]);
        }
    }
#pragma unroll
    for (int m = 0; m < 10; m++) {
        float a0, a1;
        upk2(acc[m], a0, a1);
        a0 *= 0.31622776601683794f;
        a1 *= 0.31622776601683794f;
        h[m] = pk2(__fdividef(a0, 1.f + __expf(-a0)) * 0.125f,
                   __fdividef(a1, 1.f + __expf(-a1)) * 0.125f);
    }
}

static __device__ __forceinline__ void dupd(const float* ws, int xi, float M, u64* D) {
    u64 Md = pk2(M, M);
    const ulonglong2* Fr = (const ulonglong2*)(ws + F_OFF + xi * 24);
#pragma unroll
    for (int m = 0; m < 5; m++) {
        ulonglong2 p = Fr[m];
        D[2 * m] = f2(Md, p.x, D[2 * m]);
        D[2 * m + 1] = f2(Md, p.y, D[2 * m + 1]);
    }
}

static __device__ __forceinline__ float srow(const float* ws, int xi, const u64* hp) {
    const ulonglong2* Fr = (const ulonglong2*)(ws + F_OFF + xi * 24);
    u64 s0 = 0ULL, s1 = 0ULL;
#pragma unroll
    for (int m = 0; m < 5; m++) {
        ulonglong2 p = Fr[m];
        s0 = f2(hp[2 * m], p.x, s0);
        s1 = f2(hp[2 * m + 1], p.y, s1);
    }
    float lo, hi;
    upk2(add2(s0, s1), lo, hi);
    return lo + hi;
}

// dot8 against register q, weights pre-loaded as two 16B vectors
static __device__ __forceinline__ float dot8w(ulonglong2 w01, ulonglong2 w23,
                                              const u64* q) {
    u64 p0 = mul2(w01.x, q[0]);
    p0 = f2(w01.y, q[1], p0);
    u64 p1 = mul2(w23.x, q[2]);
    p1 = f2(w23.y, q[3], p1);
    float lo, hi;
    upk2(add2(p0, p1), lo, hi);
    return lo + hi;
}

// dot8 against qv in smem (volatile: keep qv out of registers)
static __device__ __forceinline__ float dot8qv(ulonglong2 w01, ulonglong2 w23,
                                               unsigned qsh) {
    u64 q0, q1, q2, q3;
    asm volatile("ld.shared.v2.u64 {%0, %1}, [%2];"
                 : "=l"(q0), "=l"(q1) : "r"(qsh));
    asm volatile("ld.shared.v2.u64 {%0, %1}, [%2];"
                 : "=l"(q2), "=l"(q3) : "r"(qsh + 16));
    u64 p0 = mul2(w01.x, q0);
    p0 = f2(w01.y, q1, p0);
    u64 p1 = mul2(w23.x, q2);
    p1 = f2(w23.y, q3, p1);
    float lo, hi;
    upk2(add2(p0, p1), lo, hi);
    return lo + hi;
}

__global__ __launch_bounds__(NTPB, 1) void se3_main(
    const float* __restrict__ f, const float* __restrict__ pos,
    const float* __restrict__ Wk1, const float* __restrict__ Wk2,
    const float* __restrict__ Wv1, const float* __restrict__ Wv2,
    const int* __restrict__ edge_src, float* __restrict__ out) {
    extern __shared__ float sm[];
    const int tid = threadIdx.x;
    const int wid = tid >> 5, lane = tid & 31;
    const int n = blockIdx.x * NODES_PB + wid;
    const bool active = (n < NN);
    float* ws = sm + SM_NS + wid * NS_STR;

    // ---- setup: lanes 0-19 = edges; lanes 20-22 pack qv into scratch ----
    if (active) {
        if (lane < 20) {
            int e = lane;
            int src = edge_src[n * DEG + e];
            float dx = pos[src * 3 + 0] - pos[n * 3 + 0];
            float dy = pos[src * 3 + 1] - pos[n * 3 + 1];
            float dz = pos[src * 3 + 2] - pos[n * 3 + 2];
            float r2 = fmaf(dx, dx, fmaf(dy, dy, dz * dz));
            float ir = rsqrtf(r2);
            float r = r2 * ir;
            float uu[3] = {dx * ir, dy * ir, dz * ir};
            const float4* fp = (const float4*)(f + src * 32);
            float4 s0 = fp[0], s1 = fp[1];
            float gs[8] = {s0.x, s0.y, s0.z, s0.w, s1.x, s1.y, s1.z, s1.w};
            float gv[24];
            {
                float4 v0 = fp[2], v1 = fp[3], v2 = fp[4];
                float4 v3 = fp[5], v4 = fp[6], v5 = fp[7];
                gv[0]=v0.x; gv[1]=v0.y; gv[2]=v0.z; gv[3]=v0.w;
                gv[4]=v1.x; gv[5]=v1.y; gv[6]=v1.z; gv[7]=v1.w;
                gv[8]=v2.x; gv[9]=v2.y; gv[10]=v2.z; gv[11]=v2.w;
                gv[12]=v3.x; gv[13]=v3.y; gv[14]=v3.z; gv[15]=v3.w;
                gv[16]=v4.x; gv[17]=v4.y; gv[18]=v4.z; gv[19]=v4.w;
                gv[20]=v5.x; gv[21]=v5.y; gv[22]=v5.z; gv[23]=v5.w;
            }
            float* Ff = ws + F_OFF;
#pragma unroll
            for (int i = 0; i < 8; i++) {
                float gsi = gs[i];
                float g0 = gv[3 * i + 0], g1 = gv[3 * i + 1], g2 = gv[3 * i + 2];
                Ff[i * 24 + e] = gsi;
                Ff[(8 + i) * 24 + e] = fmaf(g0, uu[0], fmaf(g1, uu[1], g2 * uu[2]));
                Ff[(16 + i * 3 + 0) * 24 + e] = gsi * uu[0];
                Ff[(16 + i * 3 + 1) * 24 + e] = gsi * uu[1];
                Ff[(16 + i * 3 + 2) * 24 + e] = gsi * uu[2];
                Ff[(40 + i * 3 + 0) * 24 + e] = g0;
                Ff[(40 + i * 3 + 1) * 24 + e] = g1;
                Ff[(40 + i * 3 + 2) * 24 + e] = g2;
            }
            float rr = r * (11.0f / 3.5f);
#pragma unroll
            for (int b = 0; b < 10; b++) {
                float d = rr - (float)(b + 1);
                ws[EMB_OFF + b * 24 + e] = 26.66929f * ss(d + 1.f) * ss(1.f - d);
            }
            float x = 10.f * (1.f - r * (1.f / 3.5f));
            ws[LC_OFF + e] = (x > 0.f) ? -__fdividef(1.f, x) : -1e30f;
        } else if (lane < 23) {
            int c = lane - 20;
            const float* qf = g_qt + n * 32 + 8;
            u64* qd = (u64*)(ws + QV_OFF) + c * 4;
#pragma unroll
            for (int m = 0; m < 4; m++)
                qd[m] = pk2(qf[(2 * m) * 3 + c], qf[(2 * m + 1) * 3 + c]);
        }
    }
    stage_all(sm, Wk2, Wv2, Wk1, Wv1, tid);
    __syncthreads();

    const unsigned qv_sh = (unsigned)__cvta_generic_to_shared(ws + QV_OFF);
    const unsigned co_sh = (unsigned)__cvta_generic_to_shared(ws + CO_OFF);

    // ============ PASS 0: k-net -> logits -> coef (warp-independent) ============
    if (active) {
        const u64* W2s64 = (const u64*)sm;
        const float* W1s = sm + SM_W1K;
        u64 qq[4];
        {
            const u64* qsp = (const u64*)(g_qt + n * 32);
#pragma unroll
            for (int m = 0; m < 4; m++) qq[m] = qsp[m];
        }
        u64 Lacc[10];
#pragma unroll
        for (int m = 0; m < 10; m++) Lacc[m] = 0ULL;

#pragma unroll 1
        for (int half = 0; half < 2; half++) {
            int t = half * 32 + lane;
            u64 h[10], D[10];
            fc1_row(ws, W1s, t, h);
#pragma unroll
            for (int m = 0; m < 10; m++) D[m] = 0ULL;
            const ulonglong2* wrow2 = (const ulonglong2*)(W2s64 + t * 130);
            // paths 0,1 (xi = pi): M[2] batches, LDS.128 weights
#pragma unroll 1
            for (int g = 0; g < 8; g++) {
                ulonglong2 wa0 = wrow2[4 * g + 0], wa1 = wrow2[4 * g + 1];
                ulonglong2 wb0 = wrow2[4 * g + 2], wb1 = wrow2[4 * g + 3];
                float M0 = dot8w(wa0, wa1, qq);
                float M1 = dot8w(wb0, wb1, qq);
                dupd(ws, 2 * g, M0, D);
                dupd(ws, 2 * g + 1, M1, D);
            }
            // paths 2,3: qv from smem (volatile), LDS.128 weights
#pragma unroll 1
            for (int pi = 0; pi < 16; pi++) {
                ulonglong2 w01 = wrow2[32 + 2 * pi], w23 = wrow2[32 + 2 * pi + 1];
                int xb = 16 + (pi >> 3) * 24 + (pi & 7) * 3;
                float sc = (pi >= 8) ? 0.5773502691896258f : 1.0f;
#pragma unroll
                for (int c = 0; c < 3; c++)
                    dupd(ws, xb + c,
                         dot8qv(w01, w23, qv_sh + c * 32) * sc, D);
            }
#pragma unroll
            for (int m = 0; m < 10; m++) Lacc[m] = f2(h[m], D[m], Lacc[m]);
        }
#pragma unroll
        for (int o = 16; o >= 1; o >>= 1)
#pragma unroll
            for (int m = 0; m < 10; m++)
                Lacc[m] = add2(Lacc[m], __shfl_xor_sync(0xffffffffu, Lacc[m], o));
        if (lane == 0) {
            u64* Lg = (u64*)(ws + LG_OFF);
#pragma unroll
            for (int m = 0; m < 10; m++) Lg[m] = Lacc[m];
        }
        __syncwarp();
        {
            float L = -3.0e38f;
            if (lane < 20)
                L = fmaf(0.022097086912079608f, ws[LG_OFF + lane], ws[LC_OFF + lane]);
            float M = L;
#pragma unroll
            for (int o = 16; o >= 1; o >>= 1)
                M = fmaxf(M, __shfl_xor_sync(0xffffffffu, M, o));
            float ex = (lane < 20) ? __expf(L - M) : 0.f;
            float z = bsum(ex);
            if (lane < 20)
                ws[CO_OFF + lane] = 0.25f * sqrtf(__fdividef(ex, z) + 1e-12f);
        }
        __syncwarp();
    }

    // ============ PASS 1: v-net -> outputs (no block sync needed) ============
    if (active) {
        const u64* W2s64 = (const u64*)(sm + SM_W2V);
        const float* W1s = sm + SM_W1V;
        u64 os[4] = {0ULL, 0ULL, 0ULL, 0ULL};
        u64 ov[3][4] = {};

#pragma unroll 1
        for (int half = 0; half < 2; half++) {
            int t = half * 32 + lane;
            u64 h[10];
            fc1_row(ws, W1s, t, h);
#pragma unroll
            for (int m = 0; m < 10; m++) {
                u64 cm;
                asm volatile("ld.shared.b64 %0, [%1];"
                             : "=l"(cm) : "r"(co_sh + m * 8));
                h[m] = mul2(h[m], cm);
            }
            const ulonglong2* wrow2 = (const ulonglong2*)(W2s64 + t * 130);
            // paths 0,1 -> out_s: S[2] batches, LDS.128 weights
#pragma unroll 1
            for (int g = 0; g < 8; g++) {
                float S0 = srow(ws, 2 * g, h);
                float S1 = srow(ws, 2 * g + 1, h);
                u64 Sd0 = pk2(S0, S0), Sd1 = pk2(S1, S1);
                ulonglong2 wa0 = wrow2[4 * g + 0], wa1 = wrow2[4 * g + 1];
                ulonglong2 wb0 = wrow2[4 * g + 2], wb1 = wrow2[4 * g + 3];
                os[0] = f2(Sd0, wa0.x, os[0]);
                os[1] = f2(Sd0, wa0.y, os[1]);
                os[2] = f2(Sd0, wa1.x, os[2]);
                os[3] = f2(Sd0, wa1.y, os[3]);
                os[0] = f2(Sd1, wb0.x, os[0]);
                os[1] = f2(Sd1, wb0.y, os[1]);
                os[2] = f2(Sd1, wb1.x, os[2]);
                os[3] = f2(Sd1, wb1.y, os[3]);
            }
            // paths 2,3 -> out_v: LDS.128 weights
#pragma unroll 1
            for (int pi = 0; pi < 16; pi++) {
                ulonglong2 w01 = wrow2[32 + 2 * pi], w23 = wrow2[32 + 2 * pi + 1];
                int xb = 16 + (pi >> 3) * 24 + (pi & 7) * 3;
                float sc = (pi < 8) ? 1.7320508075688772f : 1.0f;
#pragma unroll
                for (int c = 0; c < 3; c++) {
                    float S = srow(ws, xb + c, h) * sc;
                    u64 Sd = pk2(S, S);
                    ov[c][0] = f2(Sd, w01.x, ov[c][0]);
                    ov[c][1] = f2(Sd, w01.y, ov[c][1]);
                    ov[c][2] = f2(Sd, w23.x, ov[c][2]);
                    ov[c][3] = f2(Sd, w23.y, ov[c][3]);
                }
            }
        }
#pragma unroll
        for (int o = 16; o >= 1; o >>= 1) {
#pragma unroll
            for (int r = 0; r < 4; r++)
                os[r] = add2(os[r], __shfl_xor_sync(0xffffffffu, os[r], o));
#pragma unroll
            for (int c = 0; c < 3; c++)
#pragma unroll
                for (int r = 0; r < 4; r++)
                    ov[c][r] = add2(ov[c][r], __shfl_xor_sync(0xffffffffu, ov[c][r], o));
        }
        if (lane < 4) {
            float a, b;
            upk2(os[lane], a, b);
            out[n * 32 + 2 * lane] = a;
            out[n * 32 + 2 * lane + 1] = b;
        } else if (lane < 16) {
            int idx = lane - 4;
            int c = idx >> 2, r = idx & 3;
            float a, b;
            upk2(ov[c][r], a, b);
            out[n * 32 + 8 + (2 * r) * 3 + c] = a;
            out[n * 32 + 8 + (2 * r + 1) * 3 + c] = b;
        }
    }
}

extern "C" void kernel_launch(void* const* d_in, const int* in_sizes, int n_in,
                              void* d_out, int out_size) {
    const float* f    = (const float*)d_in[0];
    const float* pos  = (const float*)d_in[1];
    const float* Wq_s = (const float*)d_in[2];
    const float* Wq_v = (const float*)d_in[3];
    const float* Wk1  = (const float*)d_in[4];
    const float* Wk2  = (const float*)d_in[5];
    const float* Wv1  = (const float*)d_in[6];
    const float* Wv2  = (const float*)d_in[7];
    const float* Wd_s = (const float*)d_in[8];
    const float* Wd_v = (const float*)d_in[9];
    const int* esrc   = (const int*)d_in[10];
    float* out = (float*)d_out;

    cudaFuncSetAttribute(se3_main, cudaFuncAttributeMaxDynamicSharedMemorySize, SMEM_BYTES);
    k0_qt<<<128, 128>>>(f, Wq_s, Wq_v, Wd_s, Wd_v);
    se3_main<<<(NN + NODES_PB - 1) / NODES_PB, NTPB, SMEM_BYTES>>>(
        f, pos, Wk1, Wk2, Wv1, Wv2, esrc, out);
}

// round 16
// speedup vs baseline: 1.3007x; 1.1415x over previous
#include <cuda_runtime.h>

#define NN 16384
#define DEG 20
typedef unsigned long long u64;

__device__ float g_qt[NN * 32];

static __device__ __forceinline__ u64 pk2(float lo, float hi) {
    u64 r; asm("mov.b64 %0, {%1, %2};" : "=l"(r) : "f"(lo), "f"(hi)); return r;
}
static __device__ __forceinline__ void upk2(u64 v, float& lo, float& hi) {
    asm("mov.b64 {%0, %1}, %2;" : "=f"(lo), "=f"(hi) : "l"(v));
}
static __device__ __forceinline__ u64 f2(u64 a, u64 b, u64 c) {
    u64 d; asm("fma.rn.f32x2 %0, %1, %2, %3;" : "=l"(d) : "l"(a), "l"(b), "l"(c)); return d;
}
static __device__ __forceinline__ u64 mul2(u64 a, u64 b) {
    u64 d; asm("mul.rn.f32x2 %0, %1, %2;" : "=l"(d) : "l"(a), "l"(b)); return d;
}
static __device__ __forceinline__ u64 add2(u64 a, u64 b) {
    u64 d; asm("add.rn.f32x2 %0, %1, %2;" : "=l"(d) : "l"(a), "l"(b)); return d;
}
static __device__ __forceinline__ float ss(float x) {
    return x > 0.f ? __expf(__fdividef(-1.f, x)) : 0.f;
}
static __device__ __forceinline__ float bsum(float v) {
#pragma unroll
    for (int o = 16; o >= 1; o >>= 1) v += __shfl_xor_sync(0xffffffffu, v, o);
    return v;
}

// ---------------- K0: fold Wq@Wd/sqrt(8) into per-node query ----------------
__global__ void k0_qt(const float* __restrict__ f, const float* __restrict__ Wq_s,
                      const float* __restrict__ Wq_v, const float* __restrict__ Wd_s,
                      const float* __restrict__ Wd_v) {
    __shared__ float As[64], Av[64];
    int t = threadIdx.x;
    if (t < 64) {
        int m = t >> 3, j = t & 7;
        float s = 0.f, v = 0.f;
#pragma unroll
        for (int o = 0; o < 8; o++) {
            s = fmaf(Wq_s[m * 8 + o], Wd_s[o * 8 + j], s);
            v = fmaf(Wq_v[m * 8 + o], Wd_v[o * 8 + j], v);
        }
        As[t] = s * 0.35355339059327373f;
        Av[t] = v * 0.35355339059327373f;
    }
    __syncthreads();
    int n = blockIdx.x * 128 + t;
    float fs[8], fv[24];
#pragma unroll
    for (int m = 0; m < 8; m++) fs[m] = f[n * 32 + m];
#pragma unroll
    for (int m = 0; m < 24; m++) fv[m] = f[n * 32 + 8 + m];
#pragma unroll
    for (int j = 0; j < 8; j++) {
        float s = 0.f;
#pragma unroll
        for (int m = 0; m < 8; m++) s = fmaf(fs[m], As[m * 8 + j], s);
        g_qt[n * 32 + j] = s;
    }
#pragma unroll
    for (int j = 0; j < 8; j++) {
        float v0 = 0.f, v1 = 0.f, v2 = 0.f;
#pragma unroll
        for (int m = 0; m < 8; m++) {
            float a = Av[m * 8 + j];
            v0 = fmaf(fv[m * 3 + 0], a, v0);
            v1 = fmaf(fv[m * 3 + 1], a, v1);
            v2 = fmaf(fv[m * 3 + 2], a, v2);
        }
        g_qt[n * 32 + 8 + j * 3 + 0] = v0;
        g_qt[n * 32 + 8 + j * 3 + 1] = v1;
        g_qt[n * 32 + 8 + j * 3 + 2] = v2;
    }
}

// smem: W2k u64[64][129] | W2v u64[64][129] | W1k 640 | W1v 640 | 12 node scratch
#define SM_W2V 16512
#define SM_W1K 33024
#define SM_W1V 33664
#define SM_NS  34304
#define NS_STR 1864
#define F_OFF   0     // [64][24] rows: gs(0-7) gd(8-15) su(16-39) gv(40-63)
#define EMB_OFF 1536  // [10][24]
#define LC_OFF  1776
#define LG_OFF  1796
#define CO_OFF  1816
#define QV_OFF  1840  // [3][4] u64 = 24 floats, 16B aligned
#define NTPB 384
#define NODES_PB 12
#define SMEM_BYTES ((SM_NS + NODES_PB * NS_STR) * 4)

static __device__ __forceinline__ void stage_all(float* sm, const float* Wk2,
                                                 const float* Wv2, const float* Wk1,
                                                 const float* Wv1, int tid) {
    u64* dk = (u64*)sm;
    u64* dv = (u64*)(sm + SM_W2V);
    const u64* sk = (const u64*)Wk2;
    const u64* sv = (const u64*)Wv2;
    for (int idx = tid; idx < 8192; idx += NTPB) {
        int o = (idx >> 7) * 129 + (idx & 127);
        dk[o] = sk[idx];
        dv[o] = sv[idx];
    }
    for (int i = tid; i < 640; i += NTPB) {
        sm[SM_W1K + i] = Wk1[i];
        sm[SM_W1V + i] = Wv1[i];
    }
}

// single-half fc1 (pass 0)
static __device__ __forceinline__ void fc1_row(const float* ws, const float* W1s,
                                               int t, u64* h) {
    u64 acc[10];
    {
        float w = W1s[t];
        u64 wd = pk2(w, w);
        const ulonglong2* Er = (const ulonglong2*)(ws + EMB_OFF);
#pragma unroll
        for (int m = 0; m < 5; m++) {
            ulonglong2 p = Er[m];
            acc[2 * m] = mul2(wd, p.x);
            acc[2 * m + 1] = mul2(wd, p.y);
        }
    }
#pragma unroll
    for (int b = 1; b < 10; b++) {
        float w = W1s[b * 64 + t];
        u64 wd = pk2(w, w);
        const ulonglong2* Er = (const ulonglong2*)(ws + EMB_OFF + b * 24);
#pragma unroll
        for (int m = 0; m < 5; m++) {
            ulonglong2 p = Er[m];
            acc[2 * m] = f2(wd, p.x, acc[2 * m]);
            acc[2 * m + 1] = f2(wd, p.y, acc[2 * m + 1]);
        }
    }
#pragma unroll
    for (int m = 0; m < 10; m++) {
        float a0, a1;
        upk2(acc[m], a0, a1);
        a0 *= 0.31622776601683794f;
        a1 *= 0.31622776601683794f;
        h[m] = pk2(__fdividef(a0, 1.f + __expf(-a0)) * 0.125f,
                   __fdividef(a1, 1.f + __expf(-a1)) * 0.125f);
    }
}

// merged-halves fc1 (pass 1): one emb sweep, both t's
static __device__ __forceinline__ void fc1_row2(const float* ws, const float* W1s,
                                                int lane, u64* h0, u64* h1) {
#pragma unroll
    for (int m = 0; m < 10; m++) { h0[m] = 0ULL; h1[m] = 0ULL; }
#pragma unroll
    for (int b = 0; b < 10; b++) {
        float wA = W1s[b * 64 + lane];
        float wB = W1s[b * 64 + 32 + lane];
        u64 wd0 = pk2(wA, wA), wd1 = pk2(wB, wB);
        const ulonglong2* Er = (const ulonglong2*)(ws + EMB_OFF + b * 24);
#pragma unroll
        for (int m = 0; m < 5; m++) {
            ulonglong2 p = Er[m];
            h0[2 * m] = f2(wd0, p.x, h0[2 * m]);
            h0[2 * m + 1] = f2(wd0, p.y, h0[2 * m + 1]);
            h1[2 * m] = f2(wd1, p.x, h1[2 * m]);
            h1[2 * m + 1] = f2(wd1, p.y, h1[2 * m + 1]);
        }
    }
#pragma unroll
    for (int m = 0; m < 10; m++) {
        float a0, a1, b0, b1;
        upk2(h0[m], a0, a1);
        upk2(h1[m], b0, b1);
        a0 *= 0.31622776601683794f; a1 *= 0.31622776601683794f;
        b0 *= 0.31622776601683794f; b1 *= 0.31622776601683794f;
        h0[m] = pk2(__fdividef(a0, 1.f + __expf(-a0)) * 0.125f,
                    __fdividef(a1, 1.f + __expf(-a1)) * 0.125f);
        h1[m] = pk2(__fdividef(b0, 1.f + __expf(-b0)) * 0.125f,
                    __fdividef(b1, 1.f + __expf(-b1)) * 0.125f);
    }
}

static __device__ __forceinline__ void dupd(const float* ws, int xi, float M, u64* D) {
    u64 Md = pk2(M, M);
    const ulonglong2* Fr = (const ulonglong2*)(ws + F_OFF + xi * 24);
#pragma unroll
    for (int m = 0; m < 5; m++) {
        ulonglong2 p = Fr[m];
        D[2 * m] = f2(Md, p.x, D[2 * m]);
        D[2 * m + 1] = f2(Md, p.y, D[2 * m + 1]);
    }
}

// merged srow: one F sweep, S for both halves
static __device__ __forceinline__ void srow2(const float* ws, int xi, const u64* h0,
                                             const u64* h1, float& S0, float& S1) {
    const ulonglong2* Fr = (const ulonglong2*)(ws + F_OFF + xi * 24);
    u64 s00 = 0ULL, s01 = 0ULL, s10 = 0ULL, s11 = 0ULL;
#pragma unroll
    for (int m = 0; m < 5; m++) {
        ulonglong2 p = Fr[m];
        s00 = f2(h0[2 * m], p.x, s00);
        s01 = f2(h0[2 * m + 1], p.y, s01);
        s10 = f2(h1[2 * m], p.x, s10);
        s11 = f2(h1[2 * m + 1], p.y, s11);
    }
    float lo, hi;
    upk2(add2(s00, s01), lo, hi);
    S0 = lo + hi;
    upk2(add2(s10, s11), lo, hi);
    S1 = lo + hi;
}

static __device__ __forceinline__ float dot8(const u64* wk, const u64* q) {
    u64 p0 = mul2(wk[0], q[0]);
    p0 = f2(wk[1], q[1], p0);
    u64 p1 = mul2(wk[2], q[2]);
    p1 = f2(wk[3], q[3], p1);
    float lo, hi;
    upk2(add2(p0, p1), lo, hi);
    return lo + hi;
}

static __device__ __forceinline__ float dot8qv(u64 w0, u64 w1, u64 w2, u64 w3,
                                               unsigned qsh) {
    u64 q0, q1, q2, q3;
    asm volatile("ld.shared.v2.u64 {%0, %1}, [%2];"
                 : "=l"(q0), "=l"(q1) : "r"(qsh));
    asm volatile("ld.shared.v2.u64 {%0, %1}, [%2];"
                 : "=l"(q2), "=l"(q3) : "r"(qsh + 16));
    u64 p0 = mul2(w0, q0);
    p0 = f2(w1, q1, p0);
    u64 p1 = mul2(w2, q2);
    p1 = f2(w3, q3, p1);
    float lo, hi;
    upk2(add2(p0, p1), lo, hi);
    return lo + hi;
}

__global__ __launch_bounds__(NTPB, 1) void se3_main(
    const float* __restrict__ f, const float* __restrict__ pos,
    const float* __restrict__ Wk1, const float* __restrict__ Wk2,
    const float* __restrict__ Wv1, const float* __restrict__ Wv2,
    const int* __restrict__ edge_src, float* __restrict__ out) {
    extern __shared__ float sm[];
    const int tid = threadIdx.x;
    const int wid = tid >> 5, lane = tid & 31;
    const int n = blockIdx.x * NODES_PB + wid;
    const bool active = (n < NN);
    float* ws = sm + SM_NS + wid * NS_STR;

    // ---- setup: lanes 0-19 = edges; lanes 20-22 pack qv into scratch ----
    if (active) {
        if (lane < 20) {
            int e = lane;
            int src = edge_src[n * DEG + e];
            float dx = pos[src * 3 + 0] - pos[n * 3 + 0];
            float dy = pos[src * 3 + 1] - pos[n * 3 + 1];
            float dz = pos[src * 3 + 2] - pos[n * 3 + 2];
            float r2 = fmaf(dx, dx, fmaf(dy, dy, dz * dz));
            float ir = rsqrtf(r2);
            float r = r2 * ir;
            float uu[3] = {dx * ir, dy * ir, dz * ir};
            const float4* fp = (const float4*)(f + src * 32);
            float4 s0 = fp[0], s1 = fp[1];
            float gs[8] = {s0.x, s0.y, s0.z, s0.w, s1.x, s1.y, s1.z, s1.w};
            float gv[24];
            {
                float4 v0 = fp[2], v1 = fp[3], v2 = fp[4];
                float4 v3 = fp[5], v4 = fp[6], v5 = fp[7];
                gv[0]=v0.x; gv[1]=v0.y; gv[2]=v0.z; gv[3]=v0.w;
                gv[4]=v1.x; gv[5]=v1.y; gv[6]=v1.z; gv[7]=v1.w;
                gv[8]=v2.x; gv[9]=v2.y; gv[10]=v2.z; gv[11]=v2.w;
                gv[12]=v3.x; gv[13]=v3.y; gv[14]=v3.z; gv[15]=v3.w;
                gv[16]=v4.x; gv[17]=v4.y; gv[18]=v4.z; gv[19]=v4.w;
                gv[20]=v5.x; gv[21]=v5.y; gv[22]=v5.z; gv[23]=v5.w;
            }
            float* Ff = ws + F_OFF;
#pragma unroll
            for (int i = 0; i < 8; i++) {
                float gsi = gs[i];
                float g0 = gv[3 * i + 0], g1 = gv[3 * i + 1], g2 = gv[3 * i + 2];
                Ff[i * 24 + e] = gsi;
                Ff[(8 + i) * 24 + e] = fmaf(g0, uu[0], fmaf(g1, uu[1], g2 * uu[2]));
                Ff[(16 + i * 3 + 0) * 24 + e] = gsi * uu[0];
                Ff[(16 + i * 3 + 1) * 24 + e] = gsi * uu[1];
                Ff[(16 + i * 3 + 2) * 24 + e] = gsi * uu[2];
                Ff[(40 + i * 3 + 0) * 24 + e] = g0;
                Ff[(40 + i * 3 + 1) * 24 + e] = g1;
                Ff[(40 + i * 3 + 2) * 24 + e] = g2;
            }
            float rr = r * (11.0f / 3.5f);
#pragma unroll
            for (int b = 0; b < 10; b++) {
                float d = rr - (float)(b + 1);
                ws[EMB_OFF + b * 24 + e] = 26.66929f * ss(d + 1.f) * ss(1.f - d);
            }
            float x = 10.f * (1.f - r * (1.f / 3.5f));
            ws[LC_OFF + e] = (x > 0.f) ? -__fdividef(1.f, x) : -1e30f;
        } else if (lane < 23) {
            int c = lane - 20;
            const float* qf = g_qt + n * 32 + 8;
            u64* qd = (u64*)(ws + QV_OFF) + c * 4;
#pragma unroll
            for (int m = 0; m < 4; m++)
                qd[m] = pk2(qf[(2 * m) * 3 + c], qf[(2 * m + 1) * 3 + c]);
        }
    }
    stage_all(sm, Wk2, Wv2, Wk1, Wv1, tid);
    __syncthreads();

    const unsigned qv_sh = (unsigned)__cvta_generic_to_shared(ws + QV_OFF);
    const unsigned co_sh = (unsigned)__cvta_generic_to_shared(ws + CO_OFF);

    // ============ PASS 0: k-net -> logits -> coef (exact R12) ============
    if (active) {
        const u64* W2s64 = (const u64*)sm;
        const float* W1s = sm + SM_W1K;
        u64 qq[4];
        {
            const u64* qsp = (const u64*)(g_qt + n * 32);
#pragma unroll
            for (int m = 0; m < 4; m++) qq[m] = qsp[m];
        }
        u64 Lacc[10];
#pragma unroll
        for (int m = 0; m < 10; m++) Lacc[m] = 0ULL;

#pragma unroll 1
        for (int half = 0; half < 2; half++) {
            int t = half * 32 + lane;
            u64 h[10], D[10];
            fc1_row(ws, W1s, t, h);
#pragma unroll
            for (int m = 0; m < 10; m++) D[m] = 0ULL;
            const u64* wrow = W2s64 + t * 129;
#pragma unroll 1
            for (int g = 0; g < 8; g++) {
                float M0 = dot8(wrow + (2 * g) * 4, qq);
                float M1 = dot8(wrow + (2 * g + 1) * 4, qq);
                dupd(ws, 2 * g, M0, D);
                dupd(ws, 2 * g + 1, M1, D);
            }
#pragma unroll 1
            for (int pi = 0; pi < 16; pi++) {
                const u64* wk = wrow + 64 + pi * 4;
                u64 w0 = wk[0], w1 = wk[1], w2 = wk[2], w3 = wk[3];
                int xb = 16 + (pi >> 3) * 24 + (pi & 7) * 3;
                float sc = (pi >= 8) ? 0.5773502691896258f : 1.0f;
#pragma unroll
                for (int c = 0; c < 3; c++)
                    dupd(ws, xb + c,
                         dot8qv(w0, w1, w2, w3, qv_sh + c * 32) * sc, D);
            }
#pragma unroll
            for (int m = 0; m < 10; m++) Lacc[m] = f2(h[m], D[m], Lacc[m]);
        }
#pragma unroll
        for (int o = 16; o >= 1; o >>= 1)
#pragma unroll
            for (int m = 0; m < 10; m++)
                Lacc[m] = add2(Lacc[m], __shfl_xor_sync(0xffffffffu, Lacc[m], o));
        if (lane == 0) {
            u64* Lg = (u64*)(ws + LG_OFF);
#pragma unroll
            for (int m = 0; m < 10; m++) Lg[m] = Lacc[m];
        }
        __syncwarp();
        {
            float L = -3.0e38f;
            if (lane < 20)
                L = fmaf(0.022097086912079608f, ws[LG_OFF + lane], ws[LC_OFF + lane]);
            float M = L;
#pragma unroll
            for (int o = 16; o >= 1; o >>= 1)
                M = fmaxf(M, __shfl_xor_sync(0xffffffffu, M, o));
            float ex = (lane < 20) ? __expf(L - M) : 0.f;
            float z = bsum(ex);
            if (lane < 20)
                ws[CO_OFF + lane] = 0.25f * sqrtf(__fdividef(ex, z) + 1e-12f);
        }
        __syncwarp();
    }

    // ============ PASS 1: v-net, merged halves (one F sweep) ============
    if (active) {
        const u64* W2s64 = (const u64*)(sm + SM_W2V);
        const float* W1s = sm + SM_W1V;
        u64 h0[10], h1[10];
        fc1_row2(ws, W1s, lane, h0, h1);
#pragma unroll
        for (int m = 0; m < 10; m++) {
            u64 cm;
            asm volatile("ld.shared.b64 %0, [%1];"
                         : "=l"(cm) : "r"(co_sh + m * 8));
            h0[m] = mul2(h0[m], cm);
            h1[m] = mul2(h1[m], cm);
        }
        const u64* wrow0 = W2s64 + lane * 129;
        const u64* wrow1 = W2s64 + (lane + 32) * 129;

        u64 os[4] = {0ULL, 0ULL, 0ULL, 0ULL};
        u64 ov[3][4] = {};

        // paths 0,1 -> out_s
#pragma unroll 1
        for (int g = 0; g < 8; g++) {
            float Sa0, Sa1, Sb0, Sb1;
            srow2(ws, 2 * g, h0, h1, Sa0, Sa1);
            srow2(ws, 2 * g + 1, h0, h1, Sb0, Sb1);
            u64 Da0 = pk2(Sa0, Sa0), Da1 = pk2(Sa1, Sa1);
            u64 Db0 = pk2(Sb0, Sb0), Db1 = pk2(Sb1, Sb1);
            const u64* wkA0 = wrow0 + (2 * g) * 4;
            const u64* wkB0 = wrow0 + (2 * g + 1) * 4;
            const u64* wkA1 = wrow1 + (2 * g) * 4;
            const u64* wkB1 = wrow1 + (2 * g + 1) * 4;
#pragma unroll
            for (int r = 0; r < 4; r++) {
                os[r] = f2(Da0, wkA0[r], os[r]);
                os[r] = f2(Db0, wkB0[r], os[r]);
                os[r] = f2(Da1, wkA1[r], os[r]);
                os[r] = f2(Db1, wkB1[r], os[r]);
            }
        }
        // paths 2,3 -> out_v
#pragma unroll 1
        for (int pi = 0; pi < 16; pi++) {
            const u64* wk0 = wrow0 + 64 + pi * 4;
            const u64* wk1 = wrow1 + 64 + pi * 4;
            int xb = 16 + (pi >> 3) * 24 + (pi & 7) * 3;
            float sc = (pi < 8) ? 1.7320508075688772f : 1.0f;
#pragma unroll
            for (int c = 0; c < 3; c++) {
                float S0, S1;
                srow2(ws, xb + c, h0, h1, S0, S1);
                S0 *= sc;
                S1 *= sc;
                u64 Sd0 = pk2(S0, S0), Sd1 = pk2(S1, S1);
#pragma unroll
                for (int r = 0; r < 4; r++) {
                    ov[c][r] = f2(Sd0, wk0[r], ov[c][r]);
                    ov[c][r] = f2(Sd1, wk1[r], ov[c][r]);
                }
            }
        }
#pragma unroll
        for (int o = 16; o >= 1; o >>= 1) {
#pragma unroll
            for (int r = 0; r < 4; r++)
                os[r] = add2(os[r], __shfl_xor_sync(0xffffffffu, os[r], o));
#pragma unroll
            for (int c = 0; c < 3; c++)
#pragma unroll
                for (int r = 0; r < 4; r++)
                    ov[c][r] = add2(ov[c][r], __shfl_xor_sync(0xffffffffu, ov[c][r], o));
        }
        if (lane < 4) {
            float a, b;
            upk2(os[lane], a, b);
            out[n * 32 + 2 * lane] = a;
            out[n * 32 + 2 * lane + 1] = b;
        } else if (lane < 16) {
            int idx = lane - 4;
            int c = idx >> 2, r = idx & 3;
            float a, b;
            upk2(ov[c][r], a, b);
            out[n * 32 + 8 + (2 * r) * 3 + c] = a;
            out[n * 32 + 8 + (2 * r + 1) * 3 + c] = b;
        }
    }
}

extern "C" void kernel_launch(void* const* d_in, const int* in_sizes, int n_in,
                              void* d_out, int out_size) {
    const float* f    = (const float*)d_in[0];
    const float* pos  = (const float*)d_in[1];
    const float* Wq_s = (const float*)d_in[2];
    const float* Wq_v = (const float*)d_in[3];
    const float* Wk1  = (const float*)d_in[4];
    const float* Wk2  = (const float*)d_in[5];
    const float* Wv1  = (const float*)d_in[6];
    const float* Wv2  = (const float*)d_in[7];
    const float* Wd_s = (const float*)d_in[8];
    const float* Wd_v = (const float*)d_in[9];
    const int* esrc   = (const int*)d_in[10];
    float* out = (float*)d_out;

    cudaFuncSetAttribute(se3_main, cudaFuncAttributeMaxDynamicSharedMemorySize, SMEM_BYTES);
    k0_qt<<<128, 128>>>(f, Wq_s, Wq_v, Wd_s, Wd_v);
    se3_main<<<(NN + NODES_PB - 1) / NODES_PB, NTPB, SMEM_BYTES>>>(
        f, pos, Wk1, Wk2, Wv1, Wv2, esrc, out);
}

// round 17
// speedup vs baseline: 1.4508x; 1.1154x over previous
#include <cuda_runtime.h>

#define NN 16384
#define DEG 20
typedef unsigned long long u64;

__device__ float g_qt[NN * 32];

static __device__ __forceinline__ u64 pk2(float lo, float hi) {
    u64 r; asm("mov.b64 %0, {%1, %2};" : "=l"(r) : "f"(lo), "f"(hi)); return r;
}
static __device__ __forceinline__ void upk2(u64 v, float& lo, float& hi) {
    asm("mov.b64 {%0, %1}, %2;" : "=f"(lo), "=f"(hi) : "l"(v));
}
static __device__ __forceinline__ u64 f2(u64 a, u64 b, u64 c) {
    u64 d; asm("fma.rn.f32x2 %0, %1, %2, %3;" : "=l"(d) : "l"(a), "l"(b), "l"(c)); return d;
}
static __device__ __forceinline__ u64 mul2(u64 a, u64 b) {
    u64 d; asm("mul.rn.f32x2 %0, %1, %2;" : "=l"(d) : "l"(a), "l"(b)); return d;
}
static __device__ __forceinline__ u64 add2(u64 a, u64 b) {
    u64 d; asm("add.rn.f32x2 %0, %1, %2;" : "=l"(d) : "l"(a), "l"(b)); return d;
}
static __device__ __forceinline__ float ss(float x) {
    return x > 0.f ? __expf(__fdividef(-1.f, x)) : 0.f;
}
static __device__ __forceinline__ float bsum(float v) {
#pragma unroll
    for (int o = 16; o >= 1; o >>= 1) v += __shfl_xor_sync(0xffffffffu, v, o);
    return v;
}

// ---------------- K0: fold Wq@Wd/sqrt(8) into per-node query ----------------
__global__ void k0_qt(const float* __restrict__ f, const float* __restrict__ Wq_s,
                      const float* __restrict__ Wq_v, const float* __restrict__ Wd_s,
                      const float* __restrict__ Wd_v) {
    __shared__ float As[64], Av[64];
    int t = threadIdx.x;
    if (t < 64) {
        int m = t >> 3, j = t & 7;
        float s = 0.f, v = 0.f;
#pragma unroll
        for (int o = 0; o < 8; o++) {
            s = fmaf(Wq_s[m * 8 + o], Wd_s[o * 8 + j], s);
            v = fmaf(Wq_v[m * 8 + o], Wd_v[o * 8 + j], v);
        }
        As[t] = s * 0.35355339059327373f;
        Av[t] = v * 0.35355339059327373f;
    }
    __syncthreads();
    int n = blockIdx.x * 128 + t;
    float fs[8], fv[24];
#pragma unroll
    for (int m = 0; m < 8; m++) fs[m] = f[n * 32 + m];
#pragma unroll
    for (int m = 0; m < 24; m++) fv[m] = f[n * 32 + 8 + m];
#pragma unroll
    for (int j = 0; j < 8; j++) {
        float s = 0.f;
#pragma unroll
        for (int m = 0; m < 8; m++) s = fmaf(fs[m], As[m * 8 + j], s);
        g_qt[n * 32 + j] = s;
    }
#pragma unroll
    for (int j = 0; j < 8; j++) {
        float v0 = 0.f, v1 = 0.f, v2 = 0.f;
#pragma unroll
        for (int m = 0; m < 8; m++) {
            float a = Av[m * 8 + j];
            v0 = fmaf(fv[m * 3 + 0], a, v0);
            v1 = fmaf(fv[m * 3 + 1], a, v1);
            v2 = fmaf(fv[m * 3 + 2], a, v2);
        }
        g_qt[n * 32 + 8 + j * 3 + 0] = v0;
        g_qt[n * 32 + 8 + j * 3 + 1] = v1;
        g_qt[n * 32 + 8 + j * 3 + 2] = v2;
    }
}

// smem: W2k u64[64][129] | W2v u64[64][129] | W1k 640 | W1v 640 | 12 node scratch
#define SM_W2V 16512
#define SM_W1K 33024
#define SM_W1V 33664
#define SM_NS  34304
#define NS_STR 1864
#define F_OFF   0     // [64][24] rows: gs(0-7) gd(8-15) su(16-39) gv(40-63)
#define EMB_OFF 1536  // [10][24]
#define LC_OFF  1776
#define LG_OFF  1796
#define CO_OFF  1816
#define QV_OFF  1840  // [3][4] u64 = 24 floats, 16B aligned
#define NTPB 384
#define NODES_PB 12
#define SMEM_BYTES ((SM_NS + NODES_PB * NS_STR) * 4)

static __device__ __forceinline__ void stage_all(float* sm, const float* Wk2,
                                                 const float* Wv2, const float* Wk1,
                                                 const float* Wv1, int tid) {
    u64* dk = (u64*)sm;
    u64* dv = (u64*)(sm + SM_W2V);
    const u64* sk = (const u64*)Wk2;
    const u64* sv = (const u64*)Wv2;
    for (int idx = tid; idx < 8192; idx += NTPB) {
        int o = (idx >> 7) * 129 + (idx & 127);
        dk[o] = sk[idx];
        dv[o] = sv[idx];
    }
    for (int i = tid; i < 640; i += NTPB) {
        sm[SM_W1K + i] = Wk1[i];
        sm[SM_W1V + i] = Wv1[i];
    }
}

// merged-halves fc1: one emb sweep, both t's (t=lane, t=lane+32)
static __device__ __forceinline__ void fc1_row2(const float* ws, const float* W1s,
                                                int lane, u64* h0, u64* h1) {
#pragma unroll
    for (int m = 0; m < 10; m++) { h0[m] = 0ULL; h1[m] = 0ULL; }
#pragma unroll
    for (int b = 0; b < 10; b++) {
        float wA = W1s[b * 64 + lane];
        float wB = W1s[b * 64 + 32 + lane];
        u64 wd0 = pk2(wA, wA), wd1 = pk2(wB, wB);
        const ulonglong2* Er = (const ulonglong2*)(ws + EMB_OFF + b * 24);
#pragma unroll
        for (int m = 0; m < 5; m++) {
            ulonglong2 p = Er[m];
            h0[2 * m] = f2(wd0, p.x, h0[2 * m]);
            h0[2 * m + 1] = f2(wd0, p.y, h0[2 * m + 1]);
            h1[2 * m] = f2(wd1, p.x, h1[2 * m]);
            h1[2 * m + 1] = f2(wd1, p.y, h1[2 * m + 1]);
        }
    }
#pragma unroll
    for (int m = 0; m < 10; m++) {
        float a0, a1, b0, b1;
        upk2(h0[m], a0, a1);
        upk2(h1[m], b0, b1);
        a0 *= 0.31622776601683794f; a1 *= 0.31622776601683794f;
        b0 *= 0.31622776601683794f; b1 *= 0.31622776601683794f;
        h0[m] = pk2(__fdividef(a0, 1.f + __expf(-a0)) * 0.125f,
                    __fdividef(a1, 1.f + __expf(-a1)) * 0.125f);
        h1[m] = pk2(__fdividef(b0, 1.f + __expf(-b0)) * 0.125f,
                    __fdividef(b1, 1.f + __expf(-b1)) * 0.125f);
    }
}

// pass-0 merged accumulate: Lacc += F[xi] * (h0*M0 + h1*M1), one F sweep
static __device__ __forceinline__ void accL(const float* ws, int xi, float M0,
                                            float M1, const u64* h0, const u64* h1,
                                            u64* Lacc) {
    u64 M0d = pk2(M0, M0), M1d = pk2(M1, M1);
    const ulonglong2* Fr = (const ulonglong2*)(ws + F_OFF + xi * 24);
#pragma unroll
    for (int m = 0; m < 5; m++) {
        ulonglong2 p = Fr[m];
        u64 Gx = f2(h0[2 * m], M0d, mul2(h1[2 * m], M1d));
        u64 Gy = f2(h0[2 * m + 1], M0d, mul2(h1[2 * m + 1], M1d));
        Lacc[2 * m] = f2(p.x, Gx, Lacc[2 * m]);
        Lacc[2 * m + 1] = f2(p.y, Gy, Lacc[2 * m + 1]);
    }
}

// merged srow: one F sweep, S for both halves
static __device__ __forceinline__ void srow2(const float* ws, int xi, const u64* h0,
                                             const u64* h1, float& S0, float& S1) {
    const ulonglong2* Fr = (const ulonglong2*)(ws + F_OFF + xi * 24);
    u64 s00 = 0ULL, s01 = 0ULL, s10 = 0ULL, s11 = 0ULL;
#pragma unroll
    for (int m = 0; m < 5; m++) {
        ulonglong2 p = Fr[m];
        s00 = f2(h0[2 * m], p.x, s00);
        s01 = f2(h0[2 * m + 1], p.y, s01);
        s10 = f2(h1[2 * m], p.x, s10);
        s11 = f2(h1[2 * m + 1], p.y, s11);
    }
    float lo, hi;
    upk2(add2(s00, s01), lo, hi);
    S0 = lo + hi;
    upk2(add2(s10, s11), lo, hi);
    S1 = lo + hi;
}

static __device__ __forceinline__ float dot8(const u64* wk, const u64* q) {
    u64 p0 = mul2(wk[0], q[0]);
    p0 = f2(wk[1], q[1], p0);
    u64 p1 = mul2(wk[2], q[2]);
    p1 = f2(wk[3], q[3], p1);
    float lo, hi;
    upk2(add2(p0, p1), lo, hi);
    return lo + hi;
}

static __device__ __forceinline__ float dot8qv(const u64* wk, unsigned qsh) {
    u64 q0, q1, q2, q3;
    asm volatile("ld.shared.v2.u64 {%0, %1}, [%2];"
                 : "=l"(q0), "=l"(q1) : "r"(qsh));
    asm volatile("ld.shared.v2.u64 {%0, %1}, [%2];"
                 : "=l"(q2), "=l"(q3) : "r"(qsh + 16));
    u64 p0 = mul2(wk[0], q0);
    p0 = f2(wk[1], q1, p0);
    u64 p1 = mul2(wk[2], q2);
    p1 = f2(wk[3], q3, p1);
    float lo, hi;
    upk2(add2(p0, p1), lo, hi);
    return lo + hi;
}

__global__ __launch_bounds__(NTPB, 1) void se3_main(
    const float* __restrict__ f, const float* __restrict__ pos,
    const float* __restrict__ Wk1, const float* __restrict__ Wk2,
    const float* __restrict__ Wv1, const float* __restrict__ Wv2,
    const int* __restrict__ edge_src, float* __restrict__ out) {
    extern __shared__ float sm[];
    const int tid = threadIdx.x;
    const int wid = tid >> 5, lane = tid & 31;
    const int n = blockIdx.x * NODES_PB + wid;
    const bool active = (n < NN);
    float* ws = sm + SM_NS + wid * NS_STR;

    // ---- setup: lanes 0-19 = edges; lanes 20-22 pack qv into scratch ----
    if (active) {
        if (lane < 20) {
            int e = lane;
            int src = edge_src[n * DEG + e];
            float dx = pos[src * 3 + 0] - pos[n * 3 + 0];
            float dy = pos[src * 3 + 1] - pos[n * 3 + 1];
            float dz = pos[src * 3 + 2] - pos[n * 3 + 2];
            float r2 = fmaf(dx, dx, fmaf(dy, dy, dz * dz));
            float ir = rsqrtf(r2);
            float r = r2 * ir;
            float uu[3] = {dx * ir, dy * ir, dz * ir};
            const float4* fp = (const float4*)(f + src * 32);
            float4 s0 = fp[0], s1 = fp[1];
            float gs[8] = {s0.x, s0.y, s0.z, s0.w, s1.x, s1.y, s1.z, s1.w};
            float gv[24];
            {
                float4 v0 = fp[2], v1 = fp[3], v2 = fp[4];
                float4 v3 = fp[5], v4 = fp[6], v5 = fp[7];
                gv[0]=v0.x; gv[1]=v0.y; gv[2]=v0.z; gv[3]=v0.w;
                gv[4]=v1.x; gv[5]=v1.y; gv[6]=v1.z; gv[7]=v1.w;
                gv[8]=v2.x; gv[9]=v2.y; gv[10]=v2.z; gv[11]=v2.w;
                gv[12]=v3.x; gv[13]=v3.y; gv[14]=v3.z; gv[15]=v3.w;
                gv[16]=v4.x; gv[17]=v4.y; gv[18]=v4.z; gv[19]=v4.w;
                gv[20]=v5.x; gv[21]=v5.y; gv[22]=v5.z; gv[23]=v5.w;
            }
            float* Ff = ws + F_OFF;
#pragma unroll
            for (int i = 0; i < 8; i++) {
                float gsi = gs[i];
                float g0 = gv[3 * i + 0], g1 = gv[3 * i + 1], g2 = gv[3 * i + 2];
                Ff[i * 24 + e] = gsi;
                Ff[(8 + i) * 24 + e] = fmaf(g0, uu[0], fmaf(g1, uu[1], g2 * uu[2]));
                Ff[(16 + i * 3 + 0) * 24 + e] = gsi * uu[0];
                Ff[(16 + i * 3 + 1) * 24 + e] = gsi * uu[1];
                Ff[(16 + i * 3 + 2) * 24 + e] = gsi * uu[2];
                Ff[(40 + i * 3 + 0) * 24 + e] = g0;
                Ff[(40 + i * 3 + 1) * 24 + e] = g1;
                Ff[(40 + i * 3 + 2) * 24 + e] = g2;
            }
            float rr = r * (11.0f / 3.5f);
#pragma unroll
            for (int b = 0; b < 10; b++) {
                float d = rr - (float)(b + 1);
                ws[EMB_OFF + b * 24 + e] = 26.66929f * ss(d + 1.f) * ss(1.f - d);
            }
            float x = 10.f * (1.f - r * (1.f / 3.5f));
            ws[LC_OFF + e] = (x > 0.f) ? -__fdividef(1.f, x) : -1e30f;
        } else if (lane < 23) {
            int c = lane - 20;
            const float* qf = g_qt + n * 32 + 8;
            u64* qd = (u64*)(ws + QV_OFF) + c * 4;
#pragma unroll
            for (int m = 0; m < 4; m++)
                qd[m] = pk2(qf[(2 * m) * 3 + c], qf[(2 * m + 1) * 3 + c]);
        }
    }
    stage_all(sm, Wk2, Wv2, Wk1, Wv1, tid);
    __syncthreads();

    const unsigned qv_sh = (unsigned)__cvta_generic_to_shared(ws + QV_OFF);
    const unsigned co_sh = (unsigned)__cvta_generic_to_shared(ws + CO_OFF);

    // ============ PASS 0: k-net -> logits -> coef (merged halves) ============
    if (active) {
        const u64* W2s64 = (const u64*)sm;
        const float* W1s = sm + SM_W1K;
        u64 qq[4];
        {
            const u64* qsp = (const u64*)(g_qt + n * 32);
#pragma unroll
            for (int m = 0; m < 4; m++) qq[m] = qsp[m];
        }
        u64 h0[10], h1[10], Lacc[10];
        fc1_row2(ws, W1s, lane, h0, h1);
#pragma unroll
        for (int m = 0; m < 10; m++) Lacc[m] = 0ULL;
        const u64* wrow0 = W2s64 + lane * 129;
        const u64* wrow1 = W2s64 + (lane + 32) * 129;

        // paths 0,1 (xi = pi)
#pragma unroll 1
        for (int pi = 0; pi < 16; pi++) {
            float M0 = dot8(wrow0 + pi * 4, qq);
            float M1 = dot8(wrow1 + pi * 4, qq);
            accL(ws, pi, M0, M1, h0, h1, Lacc);
        }
        // paths 2,3: qv from smem (volatile)
#pragma unroll 1
        for (int pi = 0; pi < 16; pi++) {
            const u64* wk0 = wrow0 + 64 + pi * 4;
            const u64* wk1 = wrow1 + 64 + pi * 4;
            int xb = 16 + (pi >> 3) * 24 + (pi & 7) * 3;
            float sc = (pi >= 8) ? 0.5773502691896258f : 1.0f;
#pragma unroll
            for (int c = 0; c < 3; c++) {
                float M0 = dot8qv(wk0, qv_sh + c * 32) * sc;
                float M1 = dot8qv(wk1, qv_sh + c * 32) * sc;
                accL(ws, xb + c, M0, M1, h0, h1, Lacc);
            }
        }
#pragma unroll
        for (int o = 16; o >= 1; o >>= 1)
#pragma unroll
            for (int m = 0; m < 10; m++)
                Lacc[m] = add2(Lacc[m], __shfl_xor_sync(0xffffffffu, Lacc[m], o));
        if (lane == 0) {
            u64* Lg = (u64*)(ws + LG_OFF);
#pragma unroll
            for (int m = 0; m < 10; m++) Lg[m] = Lacc[m];
        }
        __syncwarp();
        {
            float L = -3.0e38f;
            if (lane < 20)
                L = fmaf(0.022097086912079608f, ws[LG_OFF + lane], ws[LC_OFF + lane]);
            float M = L;
#pragma unroll
            for (int o = 16; o >= 1; o >>= 1)
                M = fmaxf(M, __shfl_xor_sync(0xffffffffu, M, o));
            float ex = (lane < 20) ? __expf(L - M) : 0.f;
            float z = bsum(ex);
            if (lane < 20)
                ws[CO_OFF + lane] = 0.25f * sqrtf(__fdividef(ex, z) + 1e-12f);
        }
        __syncwarp();
    }

    // ============ PASS 1: v-net, merged halves (one F sweep) ============
    if (active) {
        const u64* W2s64 = (const u64*)(sm + SM_W2V);
        const float* W1s = sm + SM_W1V;
        u64 h0[10], h1[10];
        fc1_row2(ws, W1s, lane, h0, h1);
#pragma unroll
        for (int m = 0; m < 10; m++) {
            u64 cm;
            asm volatile("ld.shared.b64 %0, [%1];"
                         : "=l"(cm) : "r"(co_sh + m * 8));
            h0[m] = mul2(h0[m], cm);
            h1[m] = mul2(h1[m], cm);
        }
        const u64* wrow0 = W2s64 + lane * 129;
        const u64* wrow1 = W2s64 + (lane + 32) * 129;

        u64 os[4] = {0ULL, 0ULL, 0ULL, 0ULL};
        u64 ov[3][4] = {};

        // paths 0,1 -> out_s
#pragma unroll 1
        for (int g = 0; g < 8; g++) {
            float Sa0, Sa1, Sb0, Sb1;
            srow2(ws, 2 * g, h0, h1, Sa0, Sa1);
            srow2(ws, 2 * g + 1, h0, h1, Sb0, Sb1);
            u64 Da0 = pk2(Sa0, Sa0), Da1 = pk2(Sa1, Sa1);
            u64 Db0 = pk2(Sb0, Sb0), Db1 = pk2(Sb1, Sb1);
            const u64* wkA0 = wrow0 + (2 * g) * 4;
            const u64* wkB0 = wrow0 + (2 * g + 1) * 4;
            const u64* wkA1 = wrow1 + (2 * g) * 4;
            const u64* wkB1 = wrow1 + (2 * g + 1) * 4;
#pragma unroll
            for (int r = 0; r < 4; r++) {
                os[r] = f2(Da0, wkA0[r], os[r]);
                os[r] = f2(Db0, wkB0[r], os[r]);
                os[r] = f2(Da1, wkA1[r], os[r]);
                os[r] = f2(Db1, wkB1[r], os[r]);
            }
        }
        // paths 2,3 -> out_v
#pragma unroll 1
        for (int pi = 0; pi < 16; pi++) {
            const u64* wk0 = wrow0 + 64 + pi * 4;
            const u64* wk1 = wrow1 + 64 + pi * 4;
            int xb = 16 + (pi >> 3) * 24 + (pi & 7) * 3;
            float sc = (pi < 8) ? 1.7320508075688772f : 1.0f;
#pragma unroll
            for (int c = 0; c < 3; c++) {
                float S0, S1;
                srow2(ws, xb + c, h0, h1, S0, S1);
                S0 *= sc;
                S1 *= sc;
                u64 Sd0 = pk2(S0, S0), Sd1 = pk2(S1, S1);
#pragma unroll
                for (int r = 0; r < 4; r++) {
                    ov[c][r] = f2(Sd0, wk0[r], ov[c][r]);
                    ov[c][r] = f2(Sd1, wk1[r], ov[c][r]);
                }
            }
        }
#pragma unroll
        for (int o = 16; o >= 1; o >>= 1) {
#pragma unroll
            for (int r = 0; r < 4; r++)
                os[r] = add2(os[r], __shfl_xor_sync(0xffffffffu, os[r], o));
#pragma unroll
            for (int c = 0; c < 3; c++)
#pragma unroll
                for (int r = 0; r < 4; r++)
                    ov[c][r] = add2(ov[c][r], __shfl_xor_sync(0xffffffffu, ov[c][r], o));
        }
        if (lane < 4) {
            float a, b;
            upk2(os[lane], a, b);
            out[n * 32 + 2 * lane] = a;
            out[n * 32 + 2 * lane + 1] = b;
        } else if (lane < 16) {
            int idx = lane - 4;
            int c = idx >> 2, r = idx & 3;
            float a, b;
            upk2(ov[c][r], a, b);
            out[n * 32 + 8 + (2 * r) * 3 + c] = a;
            out[n * 32 + 8 + (2 * r + 1) * 3 + c] = b;
        }
    }
}

extern "C" void kernel_launch(void* const* d_in, const int* in_sizes, int n_in,
                              void* d_out, int out_size) {
    const float* f    = (const float*)d_in[0];
    const float* pos  = (const float*)d_in[1];
    const float* Wq_s = (const float*)d_in[2];
    const float* Wq_v = (const float*)d_in[3];
    const float* Wk1  = (const float*)d_in[4];
    const float* Wk2  = (const float*)d_in[5];
    const float* Wv1  = (const float*)d_in[6];
    const float* Wv2  = (const float*)d_in[7];
    const float* Wd_s = (const float*)d_in[8];
    const float* Wd_v = (const float*)d_in[9];
    const int* esrc   = (const int*)d_in[10];
    float* out = (float*)d_out;

    cudaFuncSetAttribute(se3_main, cudaFuncAttributeMaxDynamicSharedMemorySize, SMEM_BYTES);
    k0_qt<<<128, 128>>>(f, Wq_s, Wq_v, Wd_s, Wd_v);
    se3_main<<<(NN + NODES_PB - 1) / NODES_PB, NTPB, SMEM_BYTES>>>(
        f, pos, Wk1, Wk2, Wv1, Wv2, esrc, out);
}